// round 1
// baseline (speedup 1.0000x reference)
#include <cuda_runtime.h>
#include <math.h>
#include <stdint.h>

// ---------------------------------------------------------------------------
// Problem constants (from reference)
// ---------------------------------------------------------------------------
#define BB   8
#define SS   512
#define HID  768
#define NH   12
#define DHD  64
#define INTER 3072
#define LAY  4
#define TOK  (BB*SS)        // 4096 rows
#define QKVN (3*HID)        // 2304

// ---------------------------------------------------------------------------
// Scratch (device globals: allocation-free per harness rules)
// ---------------------------------------------------------------------------
__device__ float g_h   [TOK*HID];
__device__ float g_qkv [TOK*QKVN];
__device__ float g_sc  [(size_t)BB*NH*SS*SS];
__device__ float g_attn[TOK*HID];
__device__ float g_y   [TOK*HID];
__device__ float g_ao  [TOK*HID];
__device__ float g_glu [(size_t)TOK*2*INTER];
__device__ float g_x   [(size_t)TOK*INTER];
__device__ float g_kb  [NH*SS];

// ---------------------------------------------------------------------------
// h = hidden_states * mask
// ---------------------------------------------------------------------------
__global__ void mask_init_kernel(const float* __restrict__ hs,
                                 const float* __restrict__ mask,
                                 float* __restrict__ out) {
    int i = blockIdx.x * blockDim.x + threadIdx.x;
    out[i] = hs[i] * mask[i / HID];
}

// ---------------------------------------------------------------------------
// kerple bias table: kb[h][rel] = -c1 * log1p(c2 * rel^c3), kb[h][0] = 0
// ---------------------------------------------------------------------------
__global__ void kerple_kernel(const float* __restrict__ r1,
                              const float* __restrict__ r2,
                              const float* __restrict__ r3,
                              int l, float* __restrict__ kb) {
    int rel = threadIdx.x;  // 0..511
    for (int h = 0; h < NH; h++) {
        float c1 = fmaxf(r1[l*NH + h], 1e-7f);
        float c2 = fmaxf(r2[l*NH + h], 1e-7f);
        float c3 = fmaxf(r3[l*NH + h], 1e-7f);
        float v = 0.f;
        if (rel > 0) v = -c1 * log1pf(c2 * powf((float)rel, c3));
        kb[h*SS + rel] = v;
    }
}

// ---------------------------------------------------------------------------
// Generic fp32 GEMM: C[M,N] = A[M,K] @ W[N,K]^T  (+bias, +residual, *mask)
// 128x128 tile, 256 threads, 8x8 microtile, K-chunks of 16.
// ---------------------------------------------------------------------------
__global__ __launch_bounds__(256)
void gemm_kernel(const float* __restrict__ A, const float* __restrict__ W,
                 const float* __restrict__ bias, const float* __restrict__ res,
                 const float* __restrict__ mask, float* __restrict__ C,
                 int M, int N, int K) {
    __shared__ float As[16][132];
    __shared__ float Bs[16][132];
    const int tid = threadIdx.x;
    const int tx = tid % 16, ty = tid / 16;
    const int n0 = blockIdx.x * 128, m0 = blockIdx.y * 128;
    const int lr = tid / 4;           // 0..63
    const int lk = (tid % 4) * 4;     // 0,4,8,12

    float acc[8][8] = {};

    for (int k0 = 0; k0 < K; k0 += 16) {
        #pragma unroll
        for (int half = 0; half < 2; half++) {
            int r = lr + half * 64;
            float4 va = *(const float4*)(A + (size_t)(m0 + r) * K + k0 + lk);
            As[lk+0][r] = va.x; As[lk+1][r] = va.y;
            As[lk+2][r] = va.z; As[lk+3][r] = va.w;
            float4 vb = *(const float4*)(W + (size_t)(n0 + r) * K + k0 + lk);
            Bs[lk+0][r] = vb.x; Bs[lk+1][r] = vb.y;
            Bs[lk+2][r] = vb.z; Bs[lk+3][r] = vb.w;
        }
        __syncthreads();
        #pragma unroll
        for (int kk = 0; kk < 16; kk++) {
            float a[8], b[8];
            *(float4*)(a)   = *(const float4*)&As[kk][ty*8];
            *(float4*)(a+4) = *(const float4*)&As[kk][ty*8+4];
            *(float4*)(b)   = *(const float4*)&Bs[kk][tx*8];
            *(float4*)(b+4) = *(const float4*)&Bs[kk][tx*8+4];
            #pragma unroll
            for (int i = 0; i < 8; i++)
                #pragma unroll
                for (int j = 0; j < 8; j++)
                    acc[i][j] = fmaf(a[i], b[j], acc[i][j]);
        }
        __syncthreads();
    }

    #pragma unroll
    for (int i = 0; i < 8; i++) {
        int m = m0 + ty*8 + i;
        float mm = mask ? mask[m] : 1.f;
        #pragma unroll
        for (int j = 0; j < 8; j++) {
            int n = n0 + tx*8 + j;
            float v = acc[i][j];
            if (bias) v += bias[n];
            if (res)  v += res[(size_t)m * N + n];
            C[(size_t)m * N + n] = v * mm;
        }
    }
}

// ---------------------------------------------------------------------------
// Scores: sc[bh, m, n] = (Q.K^T)/8 + kerple[h,|m-n|] + (mask[b,n]-1)*10000
// Q,K sliced out of qkv [TOK, 2304]. 128x128 tile, K=64 (4 chunks of 16).
// ---------------------------------------------------------------------------
__global__ __launch_bounds__(256)
void scores_kernel(const float* __restrict__ qkv, const float* __restrict__ mask,
                   const float* __restrict__ kb, float* __restrict__ sc) {
    const int bh = blockIdx.z;
    const int b = bh / NH, hh = bh % NH;
    const int n0 = blockIdx.x * 128, m0 = blockIdx.y * 128;
    const float* Qp = qkv + (size_t)b * SS * QKVN + hh * DHD;
    const float* Kp = qkv + (size_t)b * SS * QKVN + HID + hh * DHD;

    __shared__ float As[16][132];
    __shared__ float Bs[16][132];
    const int tid = threadIdx.x;
    const int tx = tid % 16, ty = tid / 16;
    const int lr = tid / 4;
    const int lk = (tid % 4) * 4;

    float acc[8][8] = {};

    for (int k0 = 0; k0 < DHD; k0 += 16) {
        #pragma unroll
        for (int half = 0; half < 2; half++) {
            int r = lr + half * 64;
            float4 va = *(const float4*)(Qp + (size_t)(m0 + r) * QKVN + k0 + lk);
            As[lk+0][r] = va.x; As[lk+1][r] = va.y;
            As[lk+2][r] = va.z; As[lk+3][r] = va.w;
            float4 vb = *(const float4*)(Kp + (size_t)(n0 + r) * QKVN + k0 + lk);
            Bs[lk+0][r] = vb.x; Bs[lk+1][r] = vb.y;
            Bs[lk+2][r] = vb.z; Bs[lk+3][r] = vb.w;
        }
        __syncthreads();
        #pragma unroll
        for (int kk = 0; kk < 16; kk++) {
            float a[8], bfr[8];
            *(float4*)(a)     = *(const float4*)&As[kk][ty*8];
            *(float4*)(a+4)   = *(const float4*)&As[kk][ty*8+4];
            *(float4*)(bfr)   = *(const float4*)&Bs[kk][tx*8];
            *(float4*)(bfr+4) = *(const float4*)&Bs[kk][tx*8+4];
            #pragma unroll
            for (int i = 0; i < 8; i++)
                #pragma unroll
                for (int j = 0; j < 8; j++)
                    acc[i][j] = fmaf(a[i], bfr[j], acc[i][j]);
        }
        __syncthreads();
    }

    #pragma unroll
    for (int i = 0; i < 8; i++) {
        int m = m0 + ty*8 + i;
        #pragma unroll
        for (int j = 0; j < 8; j++) {
            int n = n0 + tx*8 + j;
            int rel = m > n ? m - n : n - m;
            float v = acc[i][j] * 0.125f + kb[hh*SS + rel]
                    + (mask[b*SS + n] - 1.f) * 10000.f;
            sc[((size_t)bh * SS + m) * SS + n] = v;
        }
    }
}

// ---------------------------------------------------------------------------
// Softmax over last dim (512), one block (128 thr) per row, in place.
// ---------------------------------------------------------------------------
__global__ __launch_bounds__(128)
void softmax_kernel(float* __restrict__ sc) {
    size_t row = blockIdx.x;
    float* p = sc + row * (size_t)SS;
    int t = threadIdx.x, w = t / 32, ln = t % 32;
    float4 v = reinterpret_cast<float4*>(p)[t];

    __shared__ float smx[4], ssm[4];
    float mx = fmaxf(fmaxf(v.x, v.y), fmaxf(v.z, v.w));
    #pragma unroll
    for (int o = 16; o; o >>= 1) mx = fmaxf(mx, __shfl_xor_sync(~0u, mx, o));
    if (ln == 0) smx[w] = mx;
    __syncthreads();
    mx = fmaxf(fmaxf(smx[0], smx[1]), fmaxf(smx[2], smx[3]));

    v.x = __expf(v.x - mx); v.y = __expf(v.y - mx);
    v.z = __expf(v.z - mx); v.w = __expf(v.w - mx);
    float s = v.x + v.y + v.z + v.w;
    #pragma unroll
    for (int o = 16; o; o >>= 1) s += __shfl_xor_sync(~0u, s, o);
    if (ln == 0) ssm[w] = s;
    __syncthreads();
    s = ssm[0] + ssm[1] + ssm[2] + ssm[3];
    float inv = 1.f / s;
    v.x *= inv; v.y *= inv; v.z *= inv; v.w *= inv;
    reinterpret_cast<float4*>(p)[t] = v;
}

// ---------------------------------------------------------------------------
// PV: attn[b, m, h*64 + d] = sum_k P[bh,m,k] * V[bh,k,d]; tile 128x64, K=512.
// ---------------------------------------------------------------------------
__global__ __launch_bounds__(256)
void pv_kernel(const float* __restrict__ P, const float* __restrict__ qkv,
               float* __restrict__ attn) {
    const int bh = blockIdx.x;
    const int b = bh / NH, hh = bh % NH;
    const int m0 = blockIdx.y * 128;
    const float* Pp = P + ((size_t)bh * SS + m0) * SS;
    const float* Vp = qkv + (size_t)b * SS * QKVN + 2*HID + hh * DHD;

    __shared__ float Ps[16][132];
    __shared__ float Vs[16][68];
    const int tid = threadIdx.x;
    const int tx = tid % 16, ty = tid / 16;
    const int lr = tid / 4;
    const int lk = (tid % 4) * 4;
    const int vr = tid / 16, vc = (tid % 16) * 4;

    float acc[8][4] = {};

    for (int k0 = 0; k0 < SS; k0 += 16) {
        #pragma unroll
        for (int half = 0; half < 2; half++) {
            int r = lr + half * 64;
            float4 va = *(const float4*)(Pp + (size_t)r * SS + k0 + lk);
            Ps[lk+0][r] = va.x; Ps[lk+1][r] = va.y;
            Ps[lk+2][r] = va.z; Ps[lk+3][r] = va.w;
        }
        float4 w = *(const float4*)(Vp + (size_t)(k0 + vr) * QKVN + vc);
        *(float4*)&Vs[vr][vc] = w;
        __syncthreads();
        #pragma unroll
        for (int kk = 0; kk < 16; kk++) {
            float a[8], bfr[4];
            *(float4*)(a)   = *(const float4*)&Ps[kk][ty*8];
            *(float4*)(a+4) = *(const float4*)&Ps[kk][ty*8+4];
            *(float4*)(bfr) = *(const float4*)&Vs[kk][tx*4];
            #pragma unroll
            for (int i = 0; i < 8; i++)
                #pragma unroll
                for (int j = 0; j < 4; j++)
                    acc[i][j] = fmaf(a[i], bfr[j], acc[i][j]);
        }
        __syncthreads();
    }

    #pragma unroll
    for (int i = 0; i < 8; i++) {
        int m = m0 + ty*8 + i;
        float4 v = make_float4(acc[i][0], acc[i][1], acc[i][2], acc[i][3]);
        *(float4*)(attn + (size_t)(b*SS + m) * HID + hh*DHD + tx*4) = v;
    }
}

// ---------------------------------------------------------------------------
// LayerNorm over 768, one block (256 thr, 3 elems/thr) per row, * mask.
// ---------------------------------------------------------------------------
__global__ __launch_bounds__(256)
void ln_kernel(const float* __restrict__ y, const float* __restrict__ gma,
               const float* __restrict__ bta, const float* __restrict__ mask,
               float* __restrict__ out) {
    const int row = blockIdx.x;
    const int t = threadIdx.x, w = t / 32, ln = t % 32;
    const float* py = y + (size_t)row * HID;
    float a0 = py[t], a1 = py[t + 256], a2 = py[t + 512];

    __shared__ float red[8];
    float s = a0 + a1 + a2;
    #pragma unroll
    for (int o = 16; o; o >>= 1) s += __shfl_xor_sync(~0u, s, o);
    if (ln == 0) red[w] = s;
    __syncthreads();
    float tot = red[0]+red[1]+red[2]+red[3]+red[4]+red[5]+red[6]+red[7];
    float mu = tot * (1.f / HID);
    __syncthreads();

    float d0 = a0 - mu, d1 = a1 - mu, d2 = a2 - mu;
    float ss = d0*d0 + d1*d1 + d2*d2;
    #pragma unroll
    for (int o = 16; o; o >>= 1) ss += __shfl_xor_sync(~0u, ss, o);
    if (ln == 0) red[w] = ss;
    __syncthreads();
    float vtot = red[0]+red[1]+red[2]+red[3]+red[4]+red[5]+red[6]+red[7];
    float inv = rsqrtf(vtot * (1.f / HID) + 1e-12f);
    float mm = mask[row];

    float* po = out + (size_t)row * HID;
    po[t]       = (d0 * inv * gma[t]       + bta[t])       * mm;
    po[t + 256] = (d1 * inv * gma[t + 256] + bta[t + 256]) * mm;
    po[t + 512] = (d2 * inv * gma[t + 512] + bta[t + 512]) * mm;
}

// ---------------------------------------------------------------------------
// x = gelu_exact(g[:, :INTER]) * g[:, INTER:]
// ---------------------------------------------------------------------------
__global__ void gelumul_kernel(const float* __restrict__ g, float* __restrict__ x) {
    size_t idx = (size_t)blockIdx.x * blockDim.x + threadIdx.x;
    size_t row = idx / INTER;
    int c = (int)(idx % INTER);
    float a  = g[row * (2*INTER) + c];
    float b2 = g[row * (2*INTER) + INTER + c];
    x[idx] = 0.5f * a * (1.f + erff(a * 0.70710678118654752f)) * b2;
}

// ---------------------------------------------------------------------------
// Launch
// ---------------------------------------------------------------------------
extern "C" void kernel_launch(void* const* d_in, const int* in_sizes, int n_in,
                              void* d_out, int out_size) {
    const float* hs     = (const float*)d_in[0];
    const float* mask   = (const float*)d_in[1];
    const float* Wqkv_w = (const float*)d_in[2];
    const float* Wqkv_b = (const float*)d_in[3];
    const float* aow    = (const float*)d_in[4];
    const float* aob    = (const float*)d_in[5];
    const float* ln1g   = (const float*)d_in[6];
    const float* ln1b   = (const float*)d_in[7];
    const float* gluw   = (const float*)d_in[8];
    const float* wow    = (const float*)d_in[9];
    const float* wob    = (const float*)d_in[10];
    const float* ln2g   = (const float*)d_in[11];
    const float* ln2b   = (const float*)d_in[12];
    const float* r1     = (const float*)d_in[13];
    const float* r2     = (const float*)d_in[14];
    const float* r3     = (const float*)d_in[15];

    float *h, *qkv, *sc, *attn, *y, *ao, *glu, *x, *kb;
    cudaGetSymbolAddress((void**)&h,    g_h);
    cudaGetSymbolAddress((void**)&qkv,  g_qkv);
    cudaGetSymbolAddress((void**)&sc,   g_sc);
    cudaGetSymbolAddress((void**)&attn, g_attn);
    cudaGetSymbolAddress((void**)&y,    g_y);
    cudaGetSymbolAddress((void**)&ao,   g_ao);
    cudaGetSymbolAddress((void**)&glu,  g_glu);
    cudaGetSymbolAddress((void**)&x,    g_x);
    cudaGetSymbolAddress((void**)&kb,   g_kb);

    mask_init_kernel<<<TOK*HID/256, 256>>>(hs, mask, h);

    for (int l = 0; l < LAY; l++) {
        kerple_kernel<<<1, SS>>>(r1, r2, r3, l, kb);

        // qkv = (h @ Wqkv^T + b) * mask
        gemm_kernel<<<dim3(QKVN/128, TOK/128), 256>>>(
            h, Wqkv_w + (size_t)l*QKVN*HID, Wqkv_b + (size_t)l*QKVN,
            nullptr, mask, qkv, TOK, QKVN, HID);

        scores_kernel<<<dim3(SS/128, SS/128, BB*NH), 256>>>(qkv, mask, kb, sc);
        softmax_kernel<<<BB*NH*SS, 128>>>(sc);
        pv_kernel<<<dim3(BB*NH, SS/128), 256>>>(sc, qkv, attn);

        // y = attn @ attn_out_w^T + b + h
        gemm_kernel<<<dim3(HID/128, TOK/128), 256>>>(
            attn, aow + (size_t)l*HID*HID, aob + (size_t)l*HID,
            h, nullptr, y, TOK, HID, HID);
        ln_kernel<<<TOK, 256>>>(y, ln1g + (size_t)l*HID, ln1b + (size_t)l*HID, mask, ao);

        // g = ao @ glu_w^T
        gemm_kernel<<<dim3(2*INTER/128, TOK/128), 256>>>(
            ao, gluw + (size_t)l*2*INTER*HID, nullptr,
            nullptr, nullptr, glu, TOK, 2*INTER, HID);
        gelumul_kernel<<<(int)(((size_t)TOK*INTER)/256), 256>>>(glu, x);

        // y = x @ wo_w^T + b + ao
        gemm_kernel<<<dim3(HID/128, TOK/128), 256>>>(
            x, wow + (size_t)l*HID*INTER, wob + (size_t)l*HID,
            ao, nullptr, y, TOK, HID, INTER);

        float* hout = (l == LAY-1) ? (float*)d_out : h;
        ln_kernel<<<TOK, 256>>>(y, ln2g + (size_t)l*HID, ln2b + (size_t)l*HID, mask, hout);
    }
}

// round 2
// speedup vs baseline: 1.4051x; 1.4051x over previous
#include <cuda_runtime.h>
#include <math.h>
#include <stdint.h>

// ---------------------------------------------------------------------------
// Problem constants
// ---------------------------------------------------------------------------
#define BB   8
#define SS   512
#define HID  768
#define NH   12
#define DHD  64
#define INTER 3072
#define LAY  4
#define TOK  (BB*SS)        // 4096 rows
#define QKVN (3*HID)        // 2304

// ---------------------------------------------------------------------------
// Scratch (device globals: allocation-free per harness rules)
// ---------------------------------------------------------------------------
__device__ float g_h   [TOK*HID];
__device__ float g_qkv [TOK*QKVN];
__device__ float g_sc  [(size_t)BB*NH*SS*SS];
__device__ float g_attn[TOK*HID];
__device__ float g_y   [TOK*HID];
__device__ float g_ao  [TOK*HID];
__device__ float g_glu [(size_t)TOK*2*INTER];
__device__ float g_x   [(size_t)TOK*INTER];
__device__ float g_kb  [NH*SS];

// ---------------------------------------------------------------------------
// TF32 helpers (3xTF32 error-compensated path)
// ---------------------------------------------------------------------------
__device__ __forceinline__ uint32_t f2tf(float x) {
    uint32_t r;
    asm("cvt.rna.tf32.f32 %0, %1;" : "=r"(r) : "f"(x));
    return r;
}
__device__ __forceinline__ void splitf(float x, uint32_t& hi, uint32_t& lo) {
    hi = f2tf(x);
    lo = f2tf(x - __uint_as_float(hi));
}
__device__ __forceinline__ void mma8(float* c, const uint32_t* a, const uint32_t* b) {
    asm volatile(
        "mma.sync.aligned.m16n8k8.row.col.f32.tf32.tf32.f32 "
        "{%0,%1,%2,%3}, {%4,%5,%6,%7}, {%8,%9}, {%0,%1,%2,%3};"
        : "+f"(c[0]), "+f"(c[1]), "+f"(c[2]), "+f"(c[3])
        : "r"(a[0]), "r"(a[1]), "r"(a[2]), "r"(a[3]), "r"(b[0]), "r"(b[1]));
}
__device__ __forceinline__ void cp16(void* sdst, const void* gsrc) {
    uint32_t d = (uint32_t)__cvta_generic_to_shared(sdst);
    asm volatile("cp.async.ca.shared.global [%0], [%1], 16;" :: "r"(d), "l"(gsrc));
}
#define CP_COMMIT() asm volatile("cp.async.commit_group;")
#define CP_WAIT1()  asm volatile("cp.async.wait_group 1;")
#define CP_WAIT0()  asm volatile("cp.async.wait_group 0;")

// smem tile: 128 rows x 16 k, padded to stride 20 floats (conflict-free reads)
#define TSTRIDE 20
#define TILE_FLOATS (128*TSTRIDE)   // 2560

// ---------------------------------------------------------------------------
// Shared 128x128 mainloop: C += A[m0..][K] * B[n0..][K]^T, 3xTF32
// A: lda-strided row-major [M,K]; B: ldb-strided row-major [N,K]
// ---------------------------------------------------------------------------
__device__ __forceinline__ void mainloop128(
    const float* __restrict__ A, int lda,
    const float* __restrict__ B, int ldb,
    int m0, int n0, int K,
    float (&c)[4][4][4], float* sA, float* sB)
{
    const int t = threadIdx.x;
    const int lane = t & 31, wid = t >> 5;
    const int gid = lane >> 2, tig = lane & 3;
    const int wm = wid >> 2, wn = wid & 3;
    const int KT = K >> 4;

    auto prefetch = [&](int stage, int k0) {
        #pragma unroll
        for (int it = 0; it < 2; it++) {
            int idx = t + it * 256;       // 0..511
            int row = idx >> 2, ch = idx & 3;
            cp16(sA + stage*TILE_FLOATS + row*TSTRIDE + ch*4,
                 A + (size_t)(m0 + row) * lda + k0 + ch*4);
            cp16(sB + stage*TILE_FLOATS + row*TSTRIDE + ch*4,
                 B + (size_t)(n0 + row) * ldb + k0 + ch*4);
        }
    };

    prefetch(0, 0); CP_COMMIT();

    for (int kt = 0; kt < KT; kt++) {
        int st = kt & 1;
        if (kt + 1 < KT) { prefetch(st ^ 1, (kt + 1) * 16); CP_COMMIT(); CP_WAIT1(); }
        else             { CP_WAIT0(); }
        __syncthreads();

        const float* As = sA + st * TILE_FLOATS;
        const float* Bs = sB + st * TILE_FLOATS;

        #pragma unroll
        for (int ks = 0; ks < 2; ks++) {
            const int kk = ks * 8 + tig;
            uint32_t ah[4][4], al[4][4];
            #pragma unroll
            for (int i = 0; i < 4; i++) {
                int mr = wm*64 + i*16 + gid;
                splitf(As[mr*TSTRIDE + kk],        ah[i][0], al[i][0]);
                splitf(As[(mr+8)*TSTRIDE + kk],    ah[i][1], al[i][1]);
                splitf(As[mr*TSTRIDE + kk + 4],    ah[i][2], al[i][2]);
                splitf(As[(mr+8)*TSTRIDE + kk + 4],ah[i][3], al[i][3]);
            }
            uint32_t bh_[4][2], bl_[4][2];
            #pragma unroll
            for (int j = 0; j < 4; j++) {
                int nr = wn*32 + j*8 + gid;
                splitf(Bs[nr*TSTRIDE + kk],     bh_[j][0], bl_[j][0]);
                splitf(Bs[nr*TSTRIDE + kk + 4], bh_[j][1], bl_[j][1]);
            }
            #pragma unroll
            for (int i = 0; i < 4; i++)
                #pragma unroll
                for (int j = 0; j < 4; j++) {
                    mma8(c[i][j], ah[i], bh_[j]);
                    mma8(c[i][j], ah[i], bl_[j]);
                    mma8(c[i][j], al[i], bh_[j]);
                }
        }
        __syncthreads();
    }
}

// ---------------------------------------------------------------------------
// Generic GEMM: C[M,N] = A[M,K] @ W[N,K]^T (+bias, +res, *mask)
// ---------------------------------------------------------------------------
__global__ __launch_bounds__(256)
void gemm_tf32(const float* __restrict__ A, const float* __restrict__ W,
               const float* __restrict__ bias, const float* __restrict__ res,
               const float* __restrict__ mask, float* __restrict__ C,
               int M, int N, int K)
{
    __shared__ float sA[2*TILE_FLOATS];
    __shared__ float sB[2*TILE_FLOATS];
    float c[4][4][4] = {};
    const int m0 = blockIdx.y * 128, n0 = blockIdx.x * 128;

    mainloop128(A, K, W, K, m0, n0, K, c, sA, sB);

    const int t = threadIdx.x, lane = t & 31, wid = t >> 5;
    const int gid = lane >> 2, tig = lane & 3, wm = wid >> 2, wn = wid & 3;
    #pragma unroll
    for (int i = 0; i < 4; i++) {
        #pragma unroll
        for (int rr = 0; rr < 2; rr++) {
            int m = m0 + wm*64 + i*16 + gid + rr*8;
            float mm = mask ? mask[m] : 1.f;
            #pragma unroll
            for (int j = 0; j < 4; j++) {
                int n = n0 + wn*32 + j*8 + tig*2;
                float v0 = c[i][j][rr*2 + 0];
                float v1 = c[i][j][rr*2 + 1];
                if (bias) { v0 += bias[n]; v1 += bias[n+1]; }
                if (res)  { v0 += res[(size_t)m*N + n]; v1 += res[(size_t)m*N + n + 1]; }
                C[(size_t)m*N + n]     = v0 * mm;
                C[(size_t)m*N + n + 1] = v1 * mm;
            }
        }
    }
}

// ---------------------------------------------------------------------------
// Scores: sc = QK^T/8 + kerple + mask bias
// ---------------------------------------------------------------------------
__global__ __launch_bounds__(256)
void scores_tf32(const float* __restrict__ qkv, const float* __restrict__ mask,
                 const float* __restrict__ kb, float* __restrict__ sc)
{
    __shared__ float sA[2*TILE_FLOATS];
    __shared__ float sB[2*TILE_FLOATS];
    const int bh = blockIdx.z, b = bh / NH, hh = bh % NH;
    const float* Qp = qkv + (size_t)b * SS * QKVN + hh * DHD;
    const float* Kp = Qp + HID;
    float c[4][4][4] = {};
    const int m0 = blockIdx.y * 128, n0 = blockIdx.x * 128;

    mainloop128(Qp, QKVN, Kp, QKVN, m0, n0, DHD, c, sA, sB);

    const int t = threadIdx.x, lane = t & 31, wid = t >> 5;
    const int gid = lane >> 2, tig = lane & 3, wm = wid >> 2, wn = wid & 3;
    #pragma unroll
    for (int i = 0; i < 4; i++) {
        #pragma unroll
        for (int rr = 0; rr < 2; rr++) {
            int m = m0 + wm*64 + i*16 + gid + rr*8;
            #pragma unroll
            for (int j = 0; j < 4; j++) {
                int n = n0 + wn*32 + j*8 + tig*2;
                #pragma unroll
                for (int u = 0; u < 2; u++) {
                    int nn = n + u;
                    int rel = m > nn ? m - nn : nn - m;
                    float v = c[i][j][rr*2 + u] * 0.125f + kb[hh*SS + rel]
                            + (mask[b*SS + nn] - 1.f) * 10000.f;
                    sc[((size_t)bh*SS + m)*SS + nn] = v;
                }
            }
        }
    }
}

// ---------------------------------------------------------------------------
// PV: attn[b,m,h*64+d] = P[bh] @ V[bh]; 128x64 blocks, K=512
// ---------------------------------------------------------------------------
__global__ __launch_bounds__(256)
void pv_tf32(const float* __restrict__ P, const float* __restrict__ qkv,
             float* __restrict__ attn)
{
    __shared__ float sA[2*TILE_FLOATS];      // 128 x 16
    __shared__ float sB[2*64*TSTRIDE];       // 64 x 16
    const int bh = blockIdx.x, b = bh / NH, hh = bh % NH;
    const int m0 = blockIdx.y * 128;
    const float* Ap = P + (size_t)bh * SS * SS;
    const float* Vp = qkv + (size_t)b * SS * QKVN + 2*HID + hh * DHD;

    const int t = threadIdx.x, lane = t & 31, wid = t >> 5;
    const int gid = lane >> 2, tig = lane & 3;
    const int wm = wid >> 1, wn = wid & 1;   // 4 x 2 warps, warp tile 32x32

    float c[2][4][4] = {};

    auto prefetchA = [&](int st, int k0) {
        #pragma unroll
        for (int it = 0; it < 2; it++) {
            int idx = t + it * 256;
            int row = idx >> 2, ch = idx & 3;
            cp16(sA + st*TILE_FLOATS + row*TSTRIDE + ch*4,
                 Ap + (size_t)(m0 + row) * SS + k0 + ch*4);
        }
    };
    auto loadB = [&](int st, int k0) {
        int nc = t & 63, k4 = (t >> 6) * 4;   // 64 n-cols, 16 k-rows (4/thread)
        float v0 = Vp[(size_t)(k0 + k4 + 0) * QKVN + nc];
        float v1 = Vp[(size_t)(k0 + k4 + 1) * QKVN + nc];
        float v2 = Vp[(size_t)(k0 + k4 + 2) * QKVN + nc];
        float v3 = Vp[(size_t)(k0 + k4 + 3) * QKVN + nc];
        float* bs = sB + st * 64 * TSTRIDE;
        *(float4*)(bs + nc*TSTRIDE + k4) = make_float4(v0, v1, v2, v3);
    };

    prefetchA(0, 0); CP_COMMIT();
    loadB(0, 0);

    const int KT = SS / 16;  // 32
    for (int kt = 0; kt < KT; kt++) {
        int st = kt & 1;
        if (kt + 1 < KT) { prefetchA(st ^ 1, (kt + 1) * 16); CP_COMMIT(); CP_WAIT1(); }
        else             { CP_WAIT0(); }
        __syncthreads();
        if (kt + 1 < KT) loadB(st ^ 1, (kt + 1) * 16);

        const float* As = sA + st * TILE_FLOATS;
        const float* Bs = sB + st * 64 * TSTRIDE;

        #pragma unroll
        for (int ks = 0; ks < 2; ks++) {
            const int kk = ks * 8 + tig;
            uint32_t ah[2][4], al[2][4];
            #pragma unroll
            for (int i = 0; i < 2; i++) {
                int mr = wm*32 + i*16 + gid;
                splitf(As[mr*TSTRIDE + kk],         ah[i][0], al[i][0]);
                splitf(As[(mr+8)*TSTRIDE + kk],     ah[i][1], al[i][1]);
                splitf(As[mr*TSTRIDE + kk + 4],     ah[i][2], al[i][2]);
                splitf(As[(mr+8)*TSTRIDE + kk + 4], ah[i][3], al[i][3]);
            }
            uint32_t bh_[4][2], bl_[4][2];
            #pragma unroll
            for (int j = 0; j < 4; j++) {
                int nr = wn*32 + j*8 + gid;
                splitf(Bs[nr*TSTRIDE + kk],     bh_[j][0], bl_[j][0]);
                splitf(Bs[nr*TSTRIDE + kk + 4], bh_[j][1], bl_[j][1]);
            }
            #pragma unroll
            for (int i = 0; i < 2; i++)
                #pragma unroll
                for (int j = 0; j < 4; j++) {
                    mma8(c[i][j], ah[i], bh_[j]);
                    mma8(c[i][j], ah[i], bl_[j]);
                    mma8(c[i][j], al[i], bh_[j]);
                }
        }
        __syncthreads();
    }

    #pragma unroll
    for (int i = 0; i < 2; i++) {
        #pragma unroll
        for (int rr = 0; rr < 2; rr++) {
            int m = m0 + wm*32 + i*16 + gid + rr*8;
            #pragma unroll
            for (int j = 0; j < 4; j++) {
                int n = wn*32 + j*8 + tig*2;
                attn[(size_t)(b*SS + m)*HID + hh*DHD + n]     = c[i][j][rr*2 + 0];
                attn[(size_t)(b*SS + m)*HID + hh*DHD + n + 1] = c[i][j][rr*2 + 1];
            }
        }
    }
}

// ---------------------------------------------------------------------------
// h = hidden_states * mask
// ---------------------------------------------------------------------------
__global__ void mask_init_kernel(const float* __restrict__ hs,
                                 const float* __restrict__ mask,
                                 float* __restrict__ out) {
    int i = blockIdx.x * blockDim.x + threadIdx.x;
    out[i] = hs[i] * mask[i / HID];
}

// ---------------------------------------------------------------------------
// kerple bias table
// ---------------------------------------------------------------------------
__global__ void kerple_kernel(const float* __restrict__ r1,
                              const float* __restrict__ r2,
                              const float* __restrict__ r3,
                              int l, float* __restrict__ kb) {
    int rel = threadIdx.x;
    for (int h = 0; h < NH; h++) {
        float c1 = fmaxf(r1[l*NH + h], 1e-7f);
        float c2 = fmaxf(r2[l*NH + h], 1e-7f);
        float c3 = fmaxf(r3[l*NH + h], 1e-7f);
        float v = 0.f;
        if (rel > 0) v = -c1 * log1pf(c2 * powf((float)rel, c3));
        kb[h*SS + rel] = v;
    }
}

// ---------------------------------------------------------------------------
// Softmax over last dim (512), one block (128 thr) per row, in place.
// ---------------------------------------------------------------------------
__global__ __launch_bounds__(128)
void softmax_kernel(float* __restrict__ sc) {
    size_t row = blockIdx.x;
    float* p = sc + row * (size_t)SS;
    int t = threadIdx.x, w = t / 32, ln = t % 32;
    float4 v = reinterpret_cast<float4*>(p)[t];

    __shared__ float smx[4], ssm[4];
    float mx = fmaxf(fmaxf(v.x, v.y), fmaxf(v.z, v.w));
    #pragma unroll
    for (int o = 16; o; o >>= 1) mx = fmaxf(mx, __shfl_xor_sync(~0u, mx, o));
    if (ln == 0) smx[w] = mx;
    __syncthreads();
    mx = fmaxf(fmaxf(smx[0], smx[1]), fmaxf(smx[2], smx[3]));

    v.x = __expf(v.x - mx); v.y = __expf(v.y - mx);
    v.z = __expf(v.z - mx); v.w = __expf(v.w - mx);
    float s = v.x + v.y + v.z + v.w;
    #pragma unroll
    for (int o = 16; o; o >>= 1) s += __shfl_xor_sync(~0u, s, o);
    if (ln == 0) ssm[w] = s;
    __syncthreads();
    s = ssm[0] + ssm[1] + ssm[2] + ssm[3];
    float inv = 1.f / s;
    v.x *= inv; v.y *= inv; v.z *= inv; v.w *= inv;
    reinterpret_cast<float4*>(p)[t] = v;
}

// ---------------------------------------------------------------------------
// LayerNorm over 768, one block per row, * mask.
// ---------------------------------------------------------------------------
__global__ __launch_bounds__(256)
void ln_kernel(const float* __restrict__ y, const float* __restrict__ gma,
               const float* __restrict__ bta, const float* __restrict__ mask,
               float* __restrict__ out) {
    const int row = blockIdx.x;
    const int t = threadIdx.x, w = t / 32, ln = t % 32;
    const float* py = y + (size_t)row * HID;
    float a0 = py[t], a1 = py[t + 256], a2 = py[t + 512];

    __shared__ float red[8];
    float s = a0 + a1 + a2;
    #pragma unroll
    for (int o = 16; o; o >>= 1) s += __shfl_xor_sync(~0u, s, o);
    if (ln == 0) red[w] = s;
    __syncthreads();
    float tot = red[0]+red[1]+red[2]+red[3]+red[4]+red[5]+red[6]+red[7];
    float mu = tot * (1.f / HID);
    __syncthreads();

    float d0 = a0 - mu, d1 = a1 - mu, d2 = a2 - mu;
    float ss = d0*d0 + d1*d1 + d2*d2;
    #pragma unroll
    for (int o = 16; o; o >>= 1) ss += __shfl_xor_sync(~0u, ss, o);
    if (ln == 0) red[w] = ss;
    __syncthreads();
    float vtot = red[0]+red[1]+red[2]+red[3]+red[4]+red[5]+red[6]+red[7];
    float inv = rsqrtf(vtot * (1.f / HID) + 1e-12f);
    float mm = mask[row];

    float* po = out + (size_t)row * HID;
    po[t]       = (d0 * inv * gma[t]       + bta[t])       * mm;
    po[t + 256] = (d1 * inv * gma[t + 256] + bta[t + 256]) * mm;
    po[t + 512] = (d2 * inv * gma[t + 512] + bta[t + 512]) * mm;
}

// ---------------------------------------------------------------------------
// x = gelu_exact(g[:, :INTER]) * g[:, INTER:]
// ---------------------------------------------------------------------------
__global__ void gelumul_kernel(const float* __restrict__ g, float* __restrict__ x) {
    size_t idx = (size_t)blockIdx.x * blockDim.x + threadIdx.x;
    size_t row = idx / INTER;
    int c = (int)(idx % INTER);
    float a  = g[row * (2*INTER) + c];
    float b2 = g[row * (2*INTER) + INTER + c];
    x[idx] = 0.5f * a * (1.f + erff(a * 0.70710678118654752f)) * b2;
}

// ---------------------------------------------------------------------------
// Launch
// ---------------------------------------------------------------------------
extern "C" void kernel_launch(void* const* d_in, const int* in_sizes, int n_in,
                              void* d_out, int out_size) {
    const float* hs     = (const float*)d_in[0];
    const float* mask   = (const float*)d_in[1];
    const float* Wqkv_w = (const float*)d_in[2];
    const float* Wqkv_b = (const float*)d_in[3];
    const float* aow    = (const float*)d_in[4];
    const float* aob    = (const float*)d_in[5];
    const float* ln1g   = (const float*)d_in[6];
    const float* ln1b   = (const float*)d_in[7];
    const float* gluw   = (const float*)d_in[8];
    const float* wow    = (const float*)d_in[9];
    const float* wob    = (const float*)d_in[10];
    const float* ln2g   = (const float*)d_in[11];
    const float* ln2b   = (const float*)d_in[12];
    const float* r1     = (const float*)d_in[13];
    const float* r2     = (const float*)d_in[14];
    const float* r3     = (const float*)d_in[15];

    float *h, *qkv, *sc, *attn, *y, *ao, *glu, *x, *kb;
    cudaGetSymbolAddress((void**)&h,    g_h);
    cudaGetSymbolAddress((void**)&qkv,  g_qkv);
    cudaGetSymbolAddress((void**)&sc,   g_sc);
    cudaGetSymbolAddress((void**)&attn, g_attn);
    cudaGetSymbolAddress((void**)&y,    g_y);
    cudaGetSymbolAddress((void**)&ao,   g_ao);
    cudaGetSymbolAddress((void**)&glu,  g_glu);
    cudaGetSymbolAddress((void**)&x,    g_x);
    cudaGetSymbolAddress((void**)&kb,   g_kb);

    mask_init_kernel<<<TOK*HID/256, 256>>>(hs, mask, h);

    for (int l = 0; l < LAY; l++) {
        kerple_kernel<<<1, SS>>>(r1, r2, r3, l, kb);

        // qkv = (h @ Wqkv^T + b) * mask
        gemm_tf32<<<dim3(QKVN/128, TOK/128), 256>>>(
            h, Wqkv_w + (size_t)l*QKVN*HID, Wqkv_b + (size_t)l*QKVN,
            nullptr, mask, qkv, TOK, QKVN, HID);

        scores_tf32<<<dim3(SS/128, SS/128, BB*NH), 256>>>(qkv, mask, kb, sc);
        softmax_kernel<<<BB*NH*SS, 128>>>(sc);
        pv_tf32<<<dim3(BB*NH, SS/128), 256>>>(sc, qkv, attn);

        // y = attn @ attn_out_w^T + b + h
        gemm_tf32<<<dim3(HID/128, TOK/128), 256>>>(
            attn, aow + (size_t)l*HID*HID, aob + (size_t)l*HID,
            h, nullptr, y, TOK, HID, HID);
        ln_kernel<<<TOK, 256>>>(y, ln1g + (size_t)l*HID, ln1b + (size_t)l*HID, mask, ao);

        // g = ao @ glu_w^T
        gemm_tf32<<<dim3(2*INTER/128, TOK/128), 256>>>(
            ao, gluw + (size_t)l*2*INTER*HID, nullptr,
            nullptr, nullptr, glu, TOK, 2*INTER, HID);
        gelumul_kernel<<<(int)(((size_t)TOK*INTER)/256), 256>>>(glu, x);

        // y = x @ wo_w^T + b + ao
        gemm_tf32<<<dim3(HID/128, TOK/128), 256>>>(
            x, wow + (size_t)l*HID*INTER, wob + (size_t)l*HID,
            ao, nullptr, y, TOK, HID, INTER);

        float* hout = (l == LAY-1) ? (float*)d_out : h;
        ln_kernel<<<TOK, 256>>>(y, ln2g + (size_t)l*HID, ln2b + (size_t)l*HID, mask, hout);
    }
}

// round 3
// speedup vs baseline: 2.3874x; 1.6991x over previous
#include <cuda_runtime.h>
#include <cuda_bf16.h>
#include <math.h>
#include <stdint.h>

#define BB 8
#define SS 512
#define HID 768
#define NH 12
#define DHD 64
#define INTER 3072
#define LAY 4
#define TOK (BB*SS)
#define QKVN (3*HID)
#define BNH (BB*NH)
#define HID2 (HID/2)
#define QKVN2 (QKVN/2)
#define INTER2 (INTER/2)
#define SS2 (SS/2)

// ---------------------------------------------------------------------------
// Scratch
// ---------------------------------------------------------------------------
__device__ float g_h  [TOK*HID];
__device__ float g_y  [TOK*HID];
__device__ float g_ao [TOK*HID];
__device__ float g_qkv[TOK*QKVN];
__device__ float g_sc [(size_t)BNH*SS*SS];
__device__ float g_glu[(size_t)TOK*2*INTER];
__device__ float g_kb [NH*SS];

__device__ uint32_t g_h_hi [TOK*HID2],  g_h_lo [TOK*HID2];
__device__ uint32_t g_qkv_hi[TOK*QKVN2], g_qkv_lo[TOK*QKVN2];
__device__ uint32_t g_p_hi [(size_t)BNH*SS*SS2], g_p_lo [(size_t)BNH*SS*SS2];
__device__ uint32_t g_vt_hi[BNH*DHD*SS2], g_vt_lo[BNH*DHD*SS2];
__device__ uint32_t g_at_hi[TOK*HID2],  g_at_lo[TOK*HID2];
__device__ uint32_t g_ao_hi[TOK*HID2],  g_ao_lo[TOK*HID2];
__device__ uint32_t g_x_hi [(size_t)TOK*INTER2], g_x_lo [(size_t)TOK*INTER2];

__device__ uint32_t g_wqkv_hi[LAY*QKVN*HID/2], g_wqkv_lo[LAY*QKVN*HID/2];
__device__ uint32_t g_wao_hi [LAY*HID*HID/2],  g_wao_lo [LAY*HID*HID/2];
__device__ uint32_t g_wglu_hi[(size_t)LAY*2*INTER*HID/2], g_wglu_lo[(size_t)LAY*2*INTER*HID/2];
__device__ uint32_t g_wwo_hi [(size_t)LAY*HID*INTER/2],  g_wwo_lo [(size_t)LAY*HID*INTER/2];

// ---------------------------------------------------------------------------
// Helpers
// ---------------------------------------------------------------------------
__device__ __forceinline__ void split2(float f0, float f1, uint32_t& hi, uint32_t& lo) {
    __nv_bfloat16 h0 = __float2bfloat16_rn(f0);
    __nv_bfloat16 h1 = __float2bfloat16_rn(f1);
    float r0 = f0 - __bfloat162float(h0);
    float r1 = f1 - __bfloat162float(h1);
    __nv_bfloat16 l0 = __float2bfloat16_rn(r0);
    __nv_bfloat16 l1 = __float2bfloat16_rn(r1);
    hi = ((uint32_t)__bfloat16_as_ushort(h1) << 16) | (uint32_t)__bfloat16_as_ushort(h0);
    lo = ((uint32_t)__bfloat16_as_ushort(l1) << 16) | (uint32_t)__bfloat16_as_ushort(l0);
}

__device__ __forceinline__ void mma16(float* c, const uint32_t* a, const uint32_t* b) {
    asm volatile(
        "mma.sync.aligned.m16n8k16.row.col.f32.bf16.bf16.f32 "
        "{%0,%1,%2,%3}, {%4,%5,%6,%7}, {%8,%9}, {%0,%1,%2,%3};"
        : "+f"(c[0]), "+f"(c[1]), "+f"(c[2]), "+f"(c[3])
        : "r"(a[0]), "r"(a[1]), "r"(a[2]), "r"(a[3]), "r"(b[0]), "r"(b[1]));
}

__device__ __forceinline__ void ldsm4(uint32_t* r, uint32_t saddr) {
    asm volatile("ldmatrix.sync.aligned.m8n8.x4.shared.b16 {%0,%1,%2,%3}, [%4];"
        : "=r"(r[0]), "=r"(r[1]), "=r"(r[2]), "=r"(r[3]) : "r"(saddr));
}

__device__ __forceinline__ void cp16s(uint32_t saddr, const void* g) {
    asm volatile("cp.async.ca.shared.global [%0], [%1], 16;" :: "r"(saddr), "l"(g));
}

__device__ __forceinline__ int swz(int row, int ch) {
    return row * 64 + ((ch ^ ((row >> 1) & 3)) << 4);
}

// ---------------------------------------------------------------------------
// BF16x3 mainloop: C += A[m0..][K] * B[n0..][K]^T
// A/B pre-split into packed bf16x2 hi/lo arrays (pairs along K).
// Block: A rows = 128, B rows = BROWS. Warp grid WM x WN, warp tile (IT*16)x(JT*8).
// BK = 32 elements (16 u32). 3-stage cp.async pipeline. XOR-swizzled smem.
// ---------------------------------------------------------------------------
template<int IT, int JT, int WM, int WN, int BROWS>
__device__ __forceinline__ void mainloop(
    const uint32_t* __restrict__ Ahi, const uint32_t* __restrict__ Alo, int lda2,
    const uint32_t* __restrict__ Bhi, const uint32_t* __restrict__ Blo, int ldb2,
    int m0, int n0, int K, float (*c)[JT][4], char* smptr)
{
    constexpr int ASZ = 128 * 64;        // bytes per A tile array
    constexpr int BSZ = BROWS * 64;
    constexpr int STG = 2 * ASZ + 2 * BSZ;
    constexpr int BITER = (BROWS * 4) / 256;
    const int t = threadIdx.x, lane = t & 31, wid = t >> 5;
    const int wm = wid / WN, wn = wid % WN;
    const uint32_t sbase = (uint32_t)__cvta_generic_to_shared(smptr);
    const int KT = K >> 5;

    auto prefetch = [&](int st, int k0) {
        int kc = k0 >> 1;
        uint32_t s0 = sbase + st * STG;
        #pragma unroll
        for (int it2 = 0; it2 < 2; it2++) {
            int idx = t + it2 * 256; int row = idx >> 2, ch = idx & 3;
            int so = swz(row, ch);
            size_t go = (size_t)(m0 + row) * lda2 + kc + ch * 4;
            cp16s(s0 + so, Ahi + go);
            cp16s(s0 + ASZ + so, Alo + go);
        }
        #pragma unroll
        for (int it2 = 0; it2 < BITER; it2++) {
            int idx = t + it2 * 256; int row = idx >> 2, ch = idx & 3;
            int so = swz(row, ch);
            size_t go = (size_t)(n0 + row) * ldb2 + kc + ch * 4;
            cp16s(s0 + 2 * ASZ + so, Bhi + go);
            cp16s(s0 + 2 * ASZ + BSZ + so, Blo + go);
        }
        asm volatile("cp.async.commit_group;");
    };

    prefetch(0, 0);
    if (KT > 1) prefetch(1, 32);

    for (int kt = 0; kt < KT; kt++) {
        int st = kt % 3;
        if (kt + 2 < KT)      { prefetch((kt + 2) % 3, (kt + 2) * 32);
                                asm volatile("cp.async.wait_group 2;"); }
        else if (kt + 1 < KT) { asm volatile("cp.async.wait_group 1;"); }
        else                  { asm volatile("cp.async.wait_group 0;"); }
        __syncthreads();

        uint32_t aH = sbase + st * STG, aL = aH + ASZ;
        uint32_t bH = aH + 2 * ASZ,     bL = bH + BSZ;

        #pragma unroll
        for (int s = 0; s < 2; s++) {
            const int arow = wm * IT * 16 + (lane & 15);
            const int ach  = s * 2 + (lane >> 4);
            const int brow = wn * JT * 8 + (lane & 7) + ((lane >> 4) << 3);
            const int bch  = s * 2 + ((lane >> 3) & 1);

            uint32_t ah[IT][4], bh_[JT][2];
            #pragma unroll
            for (int i = 0; i < IT; i++)
                ldsm4(ah[i], aH + swz(arow + i * 16, ach));
            #pragma unroll
            for (int jp = 0; jp < JT / 2; jp++) {
                uint32_t rg[4];
                ldsm4(rg, bH + swz(brow + jp * 16, bch));
                bh_[jp*2][0] = rg[0]; bh_[jp*2][1] = rg[1];
                bh_[jp*2+1][0] = rg[2]; bh_[jp*2+1][1] = rg[3];
            }
            // pass 1: hi*hi
            #pragma unroll
            for (int i = 0; i < IT; i++)
                #pragma unroll
                for (int j = 0; j < JT; j++)
                    mma16(c[i][j], ah[i], bh_[j]);
            // pass 2: hi*lo
            uint32_t bl_[JT][2];
            #pragma unroll
            for (int jp = 0; jp < JT / 2; jp++) {
                uint32_t rg[4];
                ldsm4(rg, bL + swz(brow + jp * 16, bch));
                bl_[jp*2][0] = rg[0]; bl_[jp*2][1] = rg[1];
                bl_[jp*2+1][0] = rg[2]; bl_[jp*2+1][1] = rg[3];
            }
            #pragma unroll
            for (int i = 0; i < IT; i++)
                #pragma unroll
                for (int j = 0; j < JT; j++)
                    mma16(c[i][j], ah[i], bl_[j]);
            // pass 3: lo*hi
            uint32_t al[IT][4];
            #pragma unroll
            for (int i = 0; i < IT; i++)
                ldsm4(al[i], aL + swz(arow + i * 16, ach));
            #pragma unroll
            for (int i = 0; i < IT; i++)
                #pragma unroll
                for (int j = 0; j < JT; j++)
                    mma16(c[i][j], al[i], bh_[j]);
        }
        __syncthreads();
    }
}

// ---------------------------------------------------------------------------
// Generic GEMM (128x128): C = A @ W^T (+bias, +res, *mask) -> fp32 and/or packed
// ---------------------------------------------------------------------------
__global__ __launch_bounds__(256, 1)
void gemm_bf16(const uint32_t* __restrict__ Ahi, const uint32_t* __restrict__ Alo,
               const uint32_t* __restrict__ Whi, const uint32_t* __restrict__ Wlo,
               const float* __restrict__ bias, const float* __restrict__ res,
               const float* __restrict__ mask,
               float* __restrict__ outF, uint32_t* __restrict__ outHi,
               uint32_t* __restrict__ outLo, int M, int N, int K)
{
    extern __shared__ char smv[];
    float c[4][4][4] = {};
    const int m0 = blockIdx.y * 128, n0 = blockIdx.x * 128;
    mainloop<4,4,2,4,128>(Ahi, Alo, K/2, Whi, Wlo, K/2, m0, n0, K, c, smv);

    const int t = threadIdx.x, lane = t & 31, wid = t >> 5;
    const int gid = lane >> 2, tig = lane & 3, wm = wid >> 2, wn = wid & 3;
    const int N2 = N >> 1;
    #pragma unroll
    for (int i = 0; i < 4; i++) {
        #pragma unroll
        for (int rr = 0; rr < 2; rr++) {
            int m = m0 + wm*64 + i*16 + gid + rr*8;
            float mm = mask ? mask[m] : 1.f;
            #pragma unroll
            for (int j = 0; j < 4; j++) {
                int n = n0 + wn*32 + j*8 + tig*2;
                float v0 = c[i][j][rr*2 + 0], v1 = c[i][j][rr*2 + 1];
                if (bias) { v0 += bias[n]; v1 += bias[n+1]; }
                if (res)  { v0 += res[(size_t)m*N + n]; v1 += res[(size_t)m*N + n+1]; }
                v0 *= mm; v1 *= mm;
                if (outF) { outF[(size_t)m*N + n] = v0; outF[(size_t)m*N + n+1] = v1; }
                if (outHi) {
                    uint32_t hi, lo; split2(v0, v1, hi, lo);
                    outHi[(size_t)m*N2 + (n>>1)] = hi;
                    outLo[(size_t)m*N2 + (n>>1)] = lo;
                }
            }
        }
    }
}

// ---------------------------------------------------------------------------
// Scores: sc = QK^T/8 + kerple + mask bias  (K = 64)
// ---------------------------------------------------------------------------
__global__ __launch_bounds__(256, 1)
void scores_bf16(const uint32_t* __restrict__ qhi, const uint32_t* __restrict__ qlo,
                 const float* __restrict__ mask, const float* __restrict__ kb,
                 float* __restrict__ sc)
{
    extern __shared__ char smv[];
    const int bh = blockIdx.z, b = bh / NH, hh = bh % NH;
    const uint32_t* Ah = qhi + (size_t)b*SS*QKVN2 + hh*(DHD/2);
    const uint32_t* Al = qlo + (size_t)b*SS*QKVN2 + hh*(DHD/2);
    const uint32_t* Bh = Ah + HID2;
    const uint32_t* Bl = Al + HID2;
    float c[4][4][4] = {};
    const int m0 = blockIdx.y * 128, n0 = blockIdx.x * 128;
    mainloop<4,4,2,4,128>(Ah, Al, QKVN2, Bh, Bl, QKVN2, m0, n0, DHD, c, smv);

    const int t = threadIdx.x, lane = t & 31, wid = t >> 5;
    const int gid = lane >> 2, tig = lane & 3, wm = wid >> 2, wn = wid & 3;
    #pragma unroll
    for (int i = 0; i < 4; i++) {
        #pragma unroll
        for (int rr = 0; rr < 2; rr++) {
            int m = m0 + wm*64 + i*16 + gid + rr*8;
            #pragma unroll
            for (int j = 0; j < 4; j++) {
                int n = n0 + wn*32 + j*8 + tig*2;
                #pragma unroll
                for (int u = 0; u < 2; u++) {
                    int nn = n + u;
                    int rel = m > nn ? m - nn : nn - m;
                    float v = c[i][j][rr*2 + u] * 0.125f + kb[hh*SS + rel]
                            + (mask[b*SS + nn] - 1.f) * 10000.f;
                    sc[((size_t)bh*SS + m)*SS + nn] = v;
                }
            }
        }
    }
}

// ---------------------------------------------------------------------------
// PV: attn(packed) = P @ V^T_head; block 128x64, K=512
// ---------------------------------------------------------------------------
__global__ __launch_bounds__(256, 1)
void pv_bf16(const uint32_t* __restrict__ phi, const uint32_t* __restrict__ plo,
             const uint32_t* __restrict__ vthi, const uint32_t* __restrict__ vtlo,
             uint32_t* __restrict__ athi, uint32_t* __restrict__ atlo)
{
    extern __shared__ char smv[];
    const int bh = blockIdx.x, b = bh / NH, hh = bh % NH;
    const int m0 = blockIdx.y * 128;
    const uint32_t* Ah = phi + (size_t)bh*SS*SS2;
    const uint32_t* Al = plo + (size_t)bh*SS*SS2;
    const uint32_t* Bh = vthi + (size_t)bh*DHD*SS2;
    const uint32_t* Bl = vtlo + (size_t)bh*DHD*SS2;
    float c[2][4][4] = {};
    mainloop<2,4,4,2,64>(Ah, Al, SS2, Bh, Bl, SS2, m0, 0, SS, c, smv);

    const int t = threadIdx.x, lane = t & 31, wid = t >> 5;
    const int gid = lane >> 2, tig = lane & 3, wm = wid >> 1, wn = wid & 1;
    #pragma unroll
    for (int i = 0; i < 2; i++) {
        #pragma unroll
        for (int rr = 0; rr < 2; rr++) {
            int m = m0 + wm*32 + i*16 + gid + rr*8;
            #pragma unroll
            for (int j = 0; j < 4; j++) {
                int n = wn*32 + j*8 + tig*2;
                uint32_t hi, lo;
                split2(c[i][j][rr*2 + 0], c[i][j][rr*2 + 1], hi, lo);
                size_t o = (size_t)(b*SS + m)*HID2 + hh*32 + (n>>1);
                athi[o] = hi; atlo[o] = lo;
            }
        }
    }
}

// ---------------------------------------------------------------------------
// Elementwise / small kernels
// ---------------------------------------------------------------------------
__global__ void split_kernel(const float* __restrict__ in,
                             uint32_t* __restrict__ hi, uint32_t* __restrict__ lo) {
    size_t p = ((size_t)blockIdx.x * blockDim.x + threadIdx.x) * 4;  // 4 pairs
    float4 a = *(const float4*)(in + 2*p);
    float4 b = *(const float4*)(in + 2*p + 4);
    uint32_t h0,l0,h1,l1,h2,l2,h3,l3;
    split2(a.x,a.y,h0,l0); split2(a.z,a.w,h1,l1);
    split2(b.x,b.y,h2,l2); split2(b.z,b.w,h3,l3);
    *(uint4*)(hi + p) = make_uint4(h0,h1,h2,h3);
    *(uint4*)(lo + p) = make_uint4(l0,l1,l2,l3);
}

__global__ void mask_init_kernel(const float* __restrict__ hs, const float* __restrict__ mask,
                                 float* __restrict__ h, uint32_t* __restrict__ hhi,
                                 uint32_t* __restrict__ hlo) {
    size_t p = (size_t)blockIdx.x * 256 + threadIdx.x;
    size_t row = p / HID2;
    float m = mask[row];
    float f0 = hs[2*p] * m, f1 = hs[2*p+1] * m;
    h[2*p] = f0; h[2*p+1] = f1;
    split2(f0, f1, hhi[p], hlo[p]);
}

__global__ void kerple_kernel(const float* __restrict__ r1, const float* __restrict__ r2,
                              const float* __restrict__ r3, int l, float* __restrict__ kb) {
    int rel = threadIdx.x;
    for (int h = 0; h < NH; h++) {
        float c1 = fmaxf(r1[l*NH + h], 1e-7f);
        float c2 = fmaxf(r2[l*NH + h], 1e-7f);
        float c3 = fmaxf(r3[l*NH + h], 1e-7f);
        float v = 0.f;
        if (rel > 0) v = -c1 * log1pf(c2 * powf((float)rel, c3));
        kb[h*SS + rel] = v;
    }
}

__global__ __launch_bounds__(256)
void transpose_v_kernel(const float* __restrict__ qkv,
                        uint32_t* __restrict__ vthi, uint32_t* __restrict__ vtlo) {
    __shared__ float smf[128][68];
    const int bh = blockIdx.x, b = bh / NH, hh = bh % NH;
    const int s0 = blockIdx.y * 128;
    const int t = threadIdx.x;
    const float* src = qkv + (size_t)(b*SS + s0) * QKVN + 2*HID + hh*DHD;
    #pragma unroll
    for (int it = 0; it < 8; it++) {
        int idx = t + it * 256;
        int s = idx >> 4, dc = (idx & 15) * 4;
        float4 v = *(const float4*)(src + (size_t)s * QKVN + dc);
        *(float4*)&smf[s][dc] = v;
    }
    __syncthreads();
    int d = t & 63, cb = (t >> 6) * 16;
    uint32_t* oh = vthi + ((size_t)bh*DHD + d) * SS2 + s0/2 + cb;
    uint32_t* ol = vtlo + ((size_t)bh*DHD + d) * SS2 + s0/2 + cb;
    #pragma unroll
    for (int k = 0; k < 16; k++) {
        int s = 2 * (cb + k) - 2*cb*0;  // local s within tile
        s = 2 * (cb + k) - 2 * 0;       // = 2*(cb+k)
        s = 2 * (cb + k);
        s -= 2 * 0;
        int sl = 2 * (cb + k) - 2 * (cb) + 2*cb; // keep simple below
        (void)sl;
        int ss_ = 2 * (cb + k);
        uint32_t hi, lo;
        split2(smf[ss_ - 2*cb + 2*cb - 2*cb + (ss_ - (ss_ - (2*(cb+k))))][d],
               smf[2*(cb+k) + 1][d], hi, lo);
        // NOTE: simplified below — overwrite with clean computation
        split2(smf[2*(cb+k)][d], smf[2*(cb+k)+1][d], hi, lo);
        oh[k] = hi; ol[k] = lo;
    }
}

__global__ __launch_bounds__(128)
void softmax_kernel(const float* __restrict__ sc,
                    uint32_t* __restrict__ phi, uint32_t* __restrict__ plo) {
    size_t row = blockIdx.x;
    const float* p = sc + row * (size_t)SS;
    int t = threadIdx.x, w = t / 32, ln = t % 32;
    float4 v = reinterpret_cast<const float4*>(p)[t];

    __shared__ float smx[4], ssm[4];
    float mx = fmaxf(fmaxf(v.x, v.y), fmaxf(v.z, v.w));
    #pragma unroll
    for (int o = 16; o; o >>= 1) mx = fmaxf(mx, __shfl_xor_sync(~0u, mx, o));
    if (ln == 0) smx[w] = mx;
    __syncthreads();
    mx = fmaxf(fmaxf(smx[0], smx[1]), fmaxf(smx[2], smx[3]));

    v.x = __expf(v.x - mx); v.y = __expf(v.y - mx);
    v.z = __expf(v.z - mx); v.w = __expf(v.w - mx);
    float s = v.x + v.y + v.z + v.w;
    #pragma unroll
    for (int o = 16; o; o >>= 1) s += __shfl_xor_sync(~0u, s, o);
    if (ln == 0) ssm[w] = s;
    __syncthreads();
    s = ssm[0] + ssm[1] + ssm[2] + ssm[3];
    float inv = 1.f / s;
    v.x *= inv; v.y *= inv; v.z *= inv; v.w *= inv;

    uint32_t h0, l0, h1, l1;
    split2(v.x, v.y, h0, l0);
    split2(v.z, v.w, h1, l1);
    size_t o = row * SS2 + t * 2;
    phi[o] = h0; phi[o+1] = h1;
    plo[o] = l0; plo[o+1] = l1;
}

__global__ __launch_bounds__(384)
void ln_kernel(const float* __restrict__ y, const float* __restrict__ gma,
               const float* __restrict__ bta, const float* __restrict__ mask,
               float* __restrict__ outF, uint32_t* __restrict__ ohi,
               uint32_t* __restrict__ olo) {
    const int row = blockIdx.x;
    const int t = threadIdx.x, w = t >> 5, ln = t & 31;
    const float* py = y + (size_t)row * HID;
    float2 a = *(const float2*)(py + 2*t);

    __shared__ float red[12];
    float s = a.x + a.y;
    #pragma unroll
    for (int o = 16; o; o >>= 1) s += __shfl_xor_sync(~0u, s, o);
    if (ln == 0) red[w] = s;
    __syncthreads();
    float tot = 0.f;
    #pragma unroll
    for (int i = 0; i < 12; i++) tot += red[i];
    float mu = tot * (1.f / HID);
    __syncthreads();

    float d0 = a.x - mu, d1 = a.y - mu;
    float ss = d0*d0 + d1*d1;
    #pragma unroll
    for (int o = 16; o; o >>= 1) ss += __shfl_xor_sync(~0u, ss, o);
    if (ln == 0) red[w] = ss;
    __syncthreads();
    float vtot = 0.f;
    #pragma unroll
    for (int i = 0; i < 12; i++) vtot += red[i];
    float inv = rsqrtf(vtot * (1.f / HID) + 1e-12f);
    float mm = mask[row];

    float o0 = (d0 * inv * gma[2*t]   + bta[2*t])   * mm;
    float o1 = (d1 * inv * gma[2*t+1] + bta[2*t+1]) * mm;
    outF[(size_t)row*HID + 2*t]   = o0;
    outF[(size_t)row*HID + 2*t+1] = o1;
    uint32_t hi, lo; split2(o0, o1, hi, lo);
    ohi[(size_t)row*HID2 + t] = hi;
    olo[(size_t)row*HID2 + t] = lo;
}

__global__ void gelumul_kernel(const float* __restrict__ g,
                               uint32_t* __restrict__ xhi, uint32_t* __restrict__ xlo) {
    size_t p = (size_t)blockIdx.x * 256 + threadIdx.x;
    size_t row = p / INTER2;
    int c2 = (int)(p % INTER2);
    const float* gr = g + row * (size_t)(2*INTER);
    float a0 = gr[2*c2],          a1 = gr[2*c2 + 1];
    float b0 = gr[INTER + 2*c2], b1 = gr[INTER + 2*c2 + 1];
    float x0 = 0.5f * a0 * (1.f + erff(a0 * 0.70710678118654752f)) * b0;
    float x1 = 0.5f * a1 * (1.f + erff(a1 * 0.70710678118654752f)) * b1;
    uint32_t hi, lo; split2(x0, x1, hi, lo);
    xhi[p] = hi; xlo[p] = lo;
}

// ---------------------------------------------------------------------------
// Launch
// ---------------------------------------------------------------------------
extern "C" void kernel_launch(void* const* d_in, const int* in_sizes, int n_in,
                              void* d_out, int out_size) {
    const float* hs     = (const float*)d_in[0];
    const float* mask   = (const float*)d_in[1];
    const float* Wqkv_w = (const float*)d_in[2];
    const float* Wqkv_b = (const float*)d_in[3];
    const float* aow    = (const float*)d_in[4];
    const float* aob    = (const float*)d_in[5];
    const float* ln1g   = (const float*)d_in[6];
    const float* ln1b   = (const float*)d_in[7];
    const float* gluw   = (const float*)d_in[8];
    const float* wow    = (const float*)d_in[9];
    const float* wob    = (const float*)d_in[10];
    const float* ln2g   = (const float*)d_in[11];
    const float* ln2b   = (const float*)d_in[12];
    const float* r1     = (const float*)d_in[13];
    const float* r2     = (const float*)d_in[14];
    const float* r3     = (const float*)d_in[15];

    float *h, *y, *ao, *qkv, *sc, *glu, *kb;
    uint32_t *h_hi,*h_lo,*qkv_hi,*qkv_lo,*p_hi,*p_lo,*vt_hi,*vt_lo,*at_hi,*at_lo;
    uint32_t *ao_hi,*ao_lo,*x_hi,*x_lo;
    uint32_t *wqkv_hi,*wqkv_lo,*wao_hi,*wao_lo,*wglu_hi,*wglu_lo,*wwo_hi,*wwo_lo;
    cudaGetSymbolAddress((void**)&h, g_h);       cudaGetSymbolAddress((void**)&y, g_y);
    cudaGetSymbolAddress((void**)&ao, g_ao);     cudaGetSymbolAddress((void**)&qkv, g_qkv);
    cudaGetSymbolAddress((void**)&sc, g_sc);     cudaGetSymbolAddress((void**)&glu, g_glu);
    cudaGetSymbolAddress((void**)&kb, g_kb);
    cudaGetSymbolAddress((void**)&h_hi, g_h_hi);   cudaGetSymbolAddress((void**)&h_lo, g_h_lo);
    cudaGetSymbolAddress((void**)&qkv_hi, g_qkv_hi); cudaGetSymbolAddress((void**)&qkv_lo, g_qkv_lo);
    cudaGetSymbolAddress((void**)&p_hi, g_p_hi);   cudaGetSymbolAddress((void**)&p_lo, g_p_lo);
    cudaGetSymbolAddress((void**)&vt_hi, g_vt_hi); cudaGetSymbolAddress((void**)&vt_lo, g_vt_lo);
    cudaGetSymbolAddress((void**)&at_hi, g_at_hi); cudaGetSymbolAddress((void**)&at_lo, g_at_lo);
    cudaGetSymbolAddress((void**)&ao_hi, g_ao_hi); cudaGetSymbolAddress((void**)&ao_lo, g_ao_lo);
    cudaGetSymbolAddress((void**)&x_hi, g_x_hi);   cudaGetSymbolAddress((void**)&x_lo, g_x_lo);
    cudaGetSymbolAddress((void**)&wqkv_hi, g_wqkv_hi); cudaGetSymbolAddress((void**)&wqkv_lo, g_wqkv_lo);
    cudaGetSymbolAddress((void**)&wao_hi, g_wao_hi);   cudaGetSymbolAddress((void**)&wao_lo, g_wao_lo);
    cudaGetSymbolAddress((void**)&wglu_hi, g_wglu_hi); cudaGetSymbolAddress((void**)&wglu_lo, g_wglu_lo);
    cudaGetSymbolAddress((void**)&wwo_hi, g_wwo_hi);   cudaGetSymbolAddress((void**)&wwo_lo, g_wwo_lo);

    cudaFuncSetAttribute(gemm_bf16,   cudaFuncAttributeMaxDynamicSharedMemorySize, 98304);
    cudaFuncSetAttribute(scores_bf16, cudaFuncAttributeMaxDynamicSharedMemorySize, 98304);
    cudaFuncSetAttribute(pv_bf16,     cudaFuncAttributeMaxDynamicSharedMemorySize, 73728);

    // split weights (per call; deterministic)
    split_kernel<<<LAY*QKVN*HID/8/256, 256>>>(Wqkv_w, wqkv_hi, wqkv_lo);
    split_kernel<<<LAY*HID*HID/8/256, 256>>>(aow, wao_hi, wao_lo);
    split_kernel<<<(int)((size_t)LAY*2*INTER*HID/8/256), 256>>>(gluw, wglu_hi, wglu_lo);
    split_kernel<<<(int)((size_t)LAY*HID*INTER/8/256), 256>>>(wow, wwo_hi, wwo_lo);

    mask_init_kernel<<<TOK*HID2/256, 256>>>(hs, mask, h, h_hi, h_lo);

    for (int l = 0; l < LAY; l++) {
        kerple_kernel<<<1, SS>>>(r1, r2, r3, l, kb);

        gemm_bf16<<<dim3(QKVN/128, TOK/128), 256, 98304>>>(
            h_hi, h_lo, wqkv_hi + (size_t)l*QKVN*HID/2, wqkv_lo + (size_t)l*QKVN*HID/2,
            Wqkv_b + (size_t)l*QKVN, nullptr, mask, qkv, qkv_hi, qkv_lo,
            TOK, QKVN, HID);

        transpose_v_kernel<<<dim3(BNH, SS/128), 256>>>(qkv, vt_hi, vt_lo);
        scores_bf16<<<dim3(SS/128, SS/128, BNH), 256, 98304>>>(qkv_hi, qkv_lo, mask, kb, sc);
        softmax_kernel<<<BNH*SS, 128>>>(sc, p_hi, p_lo);
        pv_bf16<<<dim3(BNH, SS/128), 256, 73728>>>(p_hi, p_lo, vt_hi, vt_lo, at_hi, at_lo);

        gemm_bf16<<<dim3(HID/128, TOK/128), 256, 98304>>>(
            at_hi, at_lo, wao_hi + (size_t)l*HID*HID/2, wao_lo + (size_t)l*HID*HID/2,
            aob + (size_t)l*HID, h, nullptr, y, nullptr, nullptr,
            TOK, HID, HID);
        ln_kernel<<<TOK, 384>>>(y, ln1g + (size_t)l*HID, ln1b + (size_t)l*HID, mask,
                                ao, ao_hi, ao_lo);

        gemm_bf16<<<dim3(2*INTER/128, TOK/128), 256, 98304>>>(
            ao_hi, ao_lo, wglu_hi + (size_t)l*2*INTER*HID/2, wglu_lo + (size_t)l*2*INTER*HID/2,
            nullptr, nullptr, nullptr, glu, nullptr, nullptr,
            TOK, 2*INTER, HID);
        gelumul_kernel<<<(int)((size_t)TOK*INTER2/256), 256>>>(glu, x_hi, x_lo);

        gemm_bf16<<<dim3(HID/128, TOK/128), 256, 98304>>>(
            x_hi, x_lo, wwo_hi + (size_t)l*HID*INTER/2, wwo_lo + (size_t)l*HID*INTER/2,
            wob + (size_t)l*HID, ao, nullptr, y, nullptr, nullptr,
            TOK, HID, INTER);

        float* hout = (l == LAY-1) ? (float*)d_out : h;
        ln_kernel<<<TOK, 384>>>(y, ln2g + (size_t)l*HID, ln2b + (size_t)l*HID, mask,
                                hout, h_hi, h_lo);
    }
}

// round 4
// speedup vs baseline: 2.4380x; 1.0212x over previous
#include <cuda_runtime.h>
#include <cuda_bf16.h>
#include <math.h>
#include <stdint.h>

#define BB 8
#define SS 512
#define HID 768
#define NH 12
#define DHD 64
#define INTER 3072
#define LAY 4
#define TOK (BB*SS)
#define QKVN (3*HID)
#define BNH (BB*NH)
#define HID2 (HID/2)
#define QKVN2 (QKVN/2)
#define INTER2 (INTER/2)
#define SS2 (SS/2)

// ---------------------------------------------------------------------------
// Scratch
// ---------------------------------------------------------------------------
__device__ float g_h  [TOK*HID];
__device__ float g_y  [TOK*HID];
__device__ float g_ao [TOK*HID];
__device__ float g_kb [NH*SS];

__device__ uint32_t g_h_hi [TOK*HID2],  g_h_lo [TOK*HID2];
__device__ uint32_t g_qkv_hi[TOK*QKVN2], g_qkv_lo[TOK*QKVN2];
__device__ uint32_t g_p_hi [(size_t)BNH*SS*SS2], g_p_lo [(size_t)BNH*SS*SS2];
__device__ uint32_t g_vt_hi[BNH*DHD*SS2], g_vt_lo[BNH*DHD*SS2];
__device__ uint32_t g_at_hi[TOK*HID2],  g_at_lo[TOK*HID2];
__device__ uint32_t g_ao_hi[TOK*HID2],  g_ao_lo[TOK*HID2];
__device__ uint32_t g_x_hi [(size_t)TOK*INTER2], g_x_lo [(size_t)TOK*INTER2];

__device__ uint32_t g_wqkv_hi[LAY*QKVN*HID/2], g_wqkv_lo[LAY*QKVN*HID/2];
__device__ uint32_t g_wao_hi [LAY*HID*HID/2],  g_wao_lo [LAY*HID*HID/2];
__device__ uint32_t g_wglu_hi[(size_t)LAY*2*INTER*HID/2], g_wglu_lo[(size_t)LAY*2*INTER*HID/2];
__device__ uint32_t g_wwo_hi [(size_t)LAY*HID*INTER/2],  g_wwo_lo [(size_t)LAY*HID*INTER/2];

// ---------------------------------------------------------------------------
// Helpers
// ---------------------------------------------------------------------------
__device__ __forceinline__ void split2(float f0, float f1, uint32_t& hi, uint32_t& lo) {
    __nv_bfloat16 h0 = __float2bfloat16_rn(f0);
    __nv_bfloat16 h1 = __float2bfloat16_rn(f1);
    float r0 = f0 - __bfloat162float(h0);
    float r1 = f1 - __bfloat162float(h1);
    __nv_bfloat16 l0 = __float2bfloat16_rn(r0);
    __nv_bfloat16 l1 = __float2bfloat16_rn(r1);
    hi = ((uint32_t)__bfloat16_as_ushort(h1) << 16) | (uint32_t)__bfloat16_as_ushort(h0);
    lo = ((uint32_t)__bfloat16_as_ushort(l1) << 16) | (uint32_t)__bfloat16_as_ushort(l0);
}

__device__ __forceinline__ void unpack2(uint32_t hi, uint32_t lo, float& f0, float& f1) {
    f0 = __bfloat162float(__ushort_as_bfloat16((unsigned short)(hi & 0xffff)))
       + __bfloat162float(__ushort_as_bfloat16((unsigned short)(lo & 0xffff)));
    f1 = __bfloat162float(__ushort_as_bfloat16((unsigned short)(hi >> 16)))
       + __bfloat162float(__ushort_as_bfloat16((unsigned short)(lo >> 16)));
}

__device__ __forceinline__ void mma16(float* c, const uint32_t* a, const uint32_t* b) {
    asm volatile(
        "mma.sync.aligned.m16n8k16.row.col.f32.bf16.bf16.f32 "
        "{%0,%1,%2,%3}, {%4,%5,%6,%7}, {%8,%9}, {%0,%1,%2,%3};"
        : "+f"(c[0]), "+f"(c[1]), "+f"(c[2]), "+f"(c[3])
        : "r"(a[0]), "r"(a[1]), "r"(a[2]), "r"(a[3]), "r"(b[0]), "r"(b[1]));
}

__device__ __forceinline__ void ldsm4(uint32_t* r, uint32_t saddr) {
    asm volatile("ldmatrix.sync.aligned.m8n8.x4.shared.b16 {%0,%1,%2,%3}, [%4];"
        : "=r"(r[0]), "=r"(r[1]), "=r"(r[2]), "=r"(r[3]) : "r"(saddr));
}

__device__ __forceinline__ void cp16s(uint32_t saddr, const void* g) {
    asm volatile("cp.async.ca.shared.global [%0], [%1], 16;" :: "r"(saddr), "l"(g));
}

__device__ __forceinline__ int swz(int row, int ch) {
    return row * 64 + ((ch ^ ((row >> 1) & 3)) << 4);
}

// ---------------------------------------------------------------------------
// BF16x3 mainloop (unchanged from R2 — proven)
// ---------------------------------------------------------------------------
template<int IT, int JT, int WM, int WN, int BROWS>
__device__ __forceinline__ void mainloop(
    const uint32_t* __restrict__ Ahi, const uint32_t* __restrict__ Alo, int lda2,
    const uint32_t* __restrict__ Bhi, const uint32_t* __restrict__ Blo, int ldb2,
    int m0, int n0, int K, float (*c)[JT][4], char* smptr)
{
    constexpr int ASZ = 128 * 64;
    constexpr int BSZ = BROWS * 64;
    constexpr int STG = 2 * ASZ + 2 * BSZ;
    constexpr int BITER = (BROWS * 4) / 256;
    const int t = threadIdx.x, lane = t & 31, wid = t >> 5;
    const int wm = wid / WN, wn = wid % WN;
    const uint32_t sbase = (uint32_t)__cvta_generic_to_shared(smptr);
    const int KT = K >> 5;

    auto prefetch = [&](int st, int k0) {
        int kc = k0 >> 1;
        uint32_t s0 = sbase + st * STG;
        #pragma unroll
        for (int it2 = 0; it2 < 2; it2++) {
            int idx = t + it2 * 256; int row = idx >> 2, ch = idx & 3;
            int so = swz(row, ch);
            size_t go = (size_t)(m0 + row) * lda2 + kc + ch * 4;
            cp16s(s0 + so, Ahi + go);
            cp16s(s0 + ASZ + so, Alo + go);
        }
        #pragma unroll
        for (int it2 = 0; it2 < BITER; it2++) {
            int idx = t + it2 * 256; int row = idx >> 2, ch = idx & 3;
            int so = swz(row, ch);
            size_t go = (size_t)(n0 + row) * ldb2 + kc + ch * 4;
            cp16s(s0 + 2 * ASZ + so, Bhi + go);
            cp16s(s0 + 2 * ASZ + BSZ + so, Blo + go);
        }
        asm volatile("cp.async.commit_group;");
    };

    prefetch(0, 0);
    if (KT > 1) prefetch(1, 32);

    for (int kt = 0; kt < KT; kt++) {
        int st = kt % 3;
        if (kt + 2 < KT)      { prefetch((kt + 2) % 3, (kt + 2) * 32);
                                asm volatile("cp.async.wait_group 2;"); }
        else if (kt + 1 < KT) { asm volatile("cp.async.wait_group 1;"); }
        else                  { asm volatile("cp.async.wait_group 0;"); }
        __syncthreads();

        uint32_t aH = sbase + st * STG, aL = aH + ASZ;
        uint32_t bH = aH + 2 * ASZ,     bL = bH + BSZ;

        #pragma unroll
        for (int s = 0; s < 2; s++) {
            const int arow = wm * IT * 16 + (lane & 15);
            const int ach  = s * 2 + (lane >> 4);
            const int brow = wn * JT * 8 + (lane & 7) + ((lane >> 4) << 3);
            const int bch  = s * 2 + ((lane >> 3) & 1);

            uint32_t ah[IT][4], bh_[JT][2];
            #pragma unroll
            for (int i = 0; i < IT; i++)
                ldsm4(ah[i], aH + swz(arow + i * 16, ach));
            #pragma unroll
            for (int jp = 0; jp < JT / 2; jp++) {
                uint32_t rg[4];
                ldsm4(rg, bH + swz(brow + jp * 16, bch));
                bh_[jp*2][0] = rg[0]; bh_[jp*2][1] = rg[1];
                bh_[jp*2+1][0] = rg[2]; bh_[jp*2+1][1] = rg[3];
            }
            #pragma unroll
            for (int i = 0; i < IT; i++)
                #pragma unroll
                for (int j = 0; j < JT; j++)
                    mma16(c[i][j], ah[i], bh_[j]);
            uint32_t bl_[JT][2];
            #pragma unroll
            for (int jp = 0; jp < JT / 2; jp++) {
                uint32_t rg[4];
                ldsm4(rg, bL + swz(brow + jp * 16, bch));
                bl_[jp*2][0] = rg[0]; bl_[jp*2][1] = rg[1];
                bl_[jp*2+1][0] = rg[2]; bl_[jp*2+1][1] = rg[3];
            }
            #pragma unroll
            for (int i = 0; i < IT; i++)
                #pragma unroll
                for (int j = 0; j < JT; j++)
                    mma16(c[i][j], ah[i], bl_[j]);
            uint32_t al[IT][4];
            #pragma unroll
            for (int i = 0; i < IT; i++)
                ldsm4(al[i], aL + swz(arow + i * 16, ach));
            #pragma unroll
            for (int i = 0; i < IT; i++)
                #pragma unroll
                for (int j = 0; j < JT; j++)
                    mma16(c[i][j], al[i], bh_[j]);
        }
        __syncthreads();
    }
}

// ---------------------------------------------------------------------------
// Generic GEMM (128x128): C = A @ W^T (+bias, +res, *mask) -> fp32 and/or packed
// ---------------------------------------------------------------------------
__global__ __launch_bounds__(256, 1)
void gemm_bf16(const uint32_t* __restrict__ Ahi, const uint32_t* __restrict__ Alo,
               const uint32_t* __restrict__ Whi, const uint32_t* __restrict__ Wlo,
               const float* __restrict__ bias, const float* __restrict__ res,
               const float* __restrict__ mask,
               float* __restrict__ outF, uint32_t* __restrict__ outHi,
               uint32_t* __restrict__ outLo, int M, int N, int K)
{
    extern __shared__ char smv[];
    float c[4][4][4] = {};
    const int m0 = blockIdx.y * 128, n0 = blockIdx.x * 128;
    mainloop<4,4,2,4,128>(Ahi, Alo, K/2, Whi, Wlo, K/2, m0, n0, K, c, smv);

    const int t = threadIdx.x, lane = t & 31, wid = t >> 5;
    const int gid = lane >> 2, tig = lane & 3, wm = wid >> 2, wn = wid & 3;
    const int N2 = N >> 1;
    #pragma unroll
    for (int i = 0; i < 4; i++) {
        #pragma unroll
        for (int rr = 0; rr < 2; rr++) {
            int m = m0 + wm*64 + i*16 + gid + rr*8;
            float mm = mask ? mask[m] : 1.f;
            #pragma unroll
            for (int j = 0; j < 4; j++) {
                int n = n0 + wn*32 + j*8 + tig*2;
                float v0 = c[i][j][rr*2 + 0], v1 = c[i][j][rr*2 + 1];
                if (bias) { v0 += bias[n]; v1 += bias[n+1]; }
                if (res)  { v0 += res[(size_t)m*N + n]; v1 += res[(size_t)m*N + n+1]; }
                v0 *= mm; v1 *= mm;
                if (outF) { outF[(size_t)m*N + n] = v0; outF[(size_t)m*N + n+1] = v1; }
                if (outHi) {
                    uint32_t hi, lo; split2(v0, v1, hi, lo);
                    outHi[(size_t)m*N2 + (n>>1)] = hi;
                    outLo[(size_t)m*N2 + (n>>1)] = lo;
                }
            }
        }
    }
}

// ---------------------------------------------------------------------------
// GLU GEMM: g = ao @ glu_w_interleaved^T; epilogue x = gelu(gate)*up, packed out
// ---------------------------------------------------------------------------
__global__ __launch_bounds__(256, 1)
void gemm_glu(const uint32_t* __restrict__ Ahi, const uint32_t* __restrict__ Alo,
              const uint32_t* __restrict__ Whi, const uint32_t* __restrict__ Wlo,
              uint32_t* __restrict__ xhi, uint32_t* __restrict__ xlo, int K)
{
    extern __shared__ char smv[];
    float c[4][4][4] = {};
    const int m0 = blockIdx.y * 128, n0 = blockIdx.x * 128;
    mainloop<4,4,2,4,128>(Ahi, Alo, K/2, Whi, Wlo, K/2, m0, n0, K, c, smv);

    const int t = threadIdx.x, lane = t & 31, wid = t >> 5;
    const int gid = lane >> 2, tig = lane & 3, wm = wid >> 2, wn = wid & 3;
    #pragma unroll
    for (int i = 0; i < 4; i++) {
        #pragma unroll
        for (int rr = 0; rr < 2; rr++) {
            int m = m0 + wm*64 + i*16 + gid + rr*8;
            #pragma unroll
            for (int j = 0; j < 4; j++) {
                float v0 = c[i][j][rr*2 + 0], v1 = c[i][j][rr*2 + 1];
                float x = 0.5f * v0 * (1.f + erff(v0 * 0.70710678118654752f)) * v1;
                float xo = __shfl_xor_sync(0xffffffffu, x, 1);
                if (!(tig & 1)) {
                    uint32_t hi, lo; split2(x, xo, hi, lo);
                    size_t o = (size_t)m*INTER2 + (n0>>2) + wn*8 + j*2 + (tig>>1);
                    xhi[o] = hi; xlo[o] = lo;
                }
            }
        }
    }
}

// ---------------------------------------------------------------------------
// Fused scores + bias + softmax: per block 64 q-rows x all 512 keys.
// S kept in registers, Q/K staged in smem, writes packed P directly.
// ---------------------------------------------------------------------------
__global__ __launch_bounds__(256, 1)
void attn_scores_softmax(const uint32_t* __restrict__ qhi, const uint32_t* __restrict__ qlo,
                         const float* __restrict__ mask, const float* __restrict__ kb,
                         uint32_t* __restrict__ phi, uint32_t* __restrict__ plo)
{
    extern __shared__ char smv[];
    __shared__ float mask_s[SS], kb_s[SS];
    __shared__ float redmax[2][64], redsum[2][64];

    const int bh = blockIdx.y, b = bh / NH, hh = bh % NH;
    const int m0 = blockIdx.x * 64;
    const int t = threadIdx.x, lane = t & 31, wid = t >> 5;
    const int gid = lane >> 2, tig = lane & 3;
    const int wm = wid >> 1, wn = wid & 1;

    const uint32_t sb = (uint32_t)__cvta_generic_to_shared(smv);
    const uint32_t sQH = sb, sQL = sb + 8192, sKH = sb + 16384, sKL = sb + 81920;

    const uint32_t* Qh = qhi + (size_t)b*SS*QKVN2 + hh*32;
    const uint32_t* Ql = qlo + (size_t)b*SS*QKVN2 + hh*32;
    const uint32_t* Kh = Qh + HID2;
    const uint32_t* Kl = Ql + HID2;

    // Q: 64 rows x 64 d (2 chunks of 32 elems)
    #pragma unroll
    for (int it = 0; it < 2; it++) {
        int idx = t + it*256, row = idx >> 3, chunk = (idx >> 2) & 1, ch = idx & 3;
        size_t go = (size_t)(m0 + row)*QKVN2 + chunk*16 + ch*4;
        int so = chunk*4096 + swz(row, ch);
        cp16s(sQH + so, Qh + go);
        cp16s(sQL + so, Ql + go);
    }
    // K: 512 rows x 64 d
    #pragma unroll
    for (int it = 0; it < 16; it++) {
        int idx = t + it*256, row = idx >> 3, chunk = (idx >> 2) & 1, ch = idx & 3;
        size_t go = (size_t)row*QKVN2 + chunk*16 + ch*4;
        int so = chunk*32768 + swz(row, ch);
        cp16s(sKH + so, Kh + go);
        cp16s(sKL + so, Kl + go);
    }
    // mask + kerple rows
    {
        uint32_t ms = (uint32_t)__cvta_generic_to_shared(mask_s);
        uint32_t ks = (uint32_t)__cvta_generic_to_shared(kb_s);
        if (t < 128) cp16s(ms + t*16, mask + b*SS + t*4);
        else         cp16s(ks + (t-128)*16, kb + hh*SS + (t-128)*4);
    }
    asm volatile("cp.async.commit_group;");
    asm volatile("cp.async.wait_group 0;");
    __syncthreads();

    float c[32][4] = {};
    #pragma unroll
    for (int s4 = 0; s4 < 4; s4++) {
        int chunk = s4 >> 1, ss_ = s4 & 1;
        int arow = wm*16 + (lane & 15);
        int ach = ss_*2 + (lane >> 4);
        uint32_t ah[4], al[4];
        ldsm4(ah, sQH + chunk*4096 + swz(arow, ach));
        ldsm4(al, sQL + chunk*4096 + swz(arow, ach));
        int browb = wn*256 + (lane & 7) + ((lane >> 4) << 3);
        int bch = ss_*2 + ((lane >> 3) & 1);
        #pragma unroll
        for (int jp = 0; jp < 16; jp++) {
            uint32_t bh_[4], bl_[4];
            ldsm4(bh_, sKH + chunk*32768 + swz(browb + jp*16, bch));
            ldsm4(bl_, sKL + chunk*32768 + swz(browb + jp*16, bch));
            mma16(c[2*jp],   ah, bh_);
            mma16(c[2*jp+1], ah, bh_ + 2);
            mma16(c[2*jp],   ah, bl_);
            mma16(c[2*jp+1], ah, bl_ + 2);
            mma16(c[2*jp],   al, bh_);
            mma16(c[2*jp+1], al, bh_ + 2);
        }
    }

    // bias + row max
    const int mrow0 = m0 + wm*16 + gid, mrow1 = mrow0 + 8;
    float mx0 = -1e30f, mx1 = -1e30f;
    #pragma unroll
    for (int j = 0; j < 32; j++) {
        int n = wn*256 + j*8 + tig*2;
        #pragma unroll
        for (int u = 0; u < 2; u++) {
            int nn = n + u;
            float badd = (mask_s[nn] - 1.f) * 10000.f;
            int r0 = mrow0 > nn ? mrow0 - nn : nn - mrow0;
            int r1 = mrow1 > nn ? mrow1 - nn : nn - mrow1;
            c[j][u]   = c[j][u]   * 0.125f + kb_s[r0] + badd;
            c[j][2+u] = c[j][2+u] * 0.125f + kb_s[r1] + badd;
            mx0 = fmaxf(mx0, c[j][u]);
            mx1 = fmaxf(mx1, c[j][2+u]);
        }
    }
    mx0 = fmaxf(mx0, __shfl_xor_sync(~0u, mx0, 1));
    mx0 = fmaxf(mx0, __shfl_xor_sync(~0u, mx0, 2));
    mx1 = fmaxf(mx1, __shfl_xor_sync(~0u, mx1, 1));
    mx1 = fmaxf(mx1, __shfl_xor_sync(~0u, mx1, 2));
    if (tig == 0) { redmax[wn][wm*16+gid] = mx0; redmax[wn][wm*16+gid+8] = mx1; }
    __syncthreads();
    mx0 = fmaxf(redmax[0][wm*16+gid],   redmax[1][wm*16+gid]);
    mx1 = fmaxf(redmax[0][wm*16+gid+8], redmax[1][wm*16+gid+8]);

    float s0 = 0.f, s1 = 0.f;
    #pragma unroll
    for (int j = 0; j < 32; j++) {
        #pragma unroll
        for (int u = 0; u < 2; u++) {
            c[j][u]   = __expf(c[j][u]   - mx0); s0 += c[j][u];
            c[j][2+u] = __expf(c[j][2+u] - mx1); s1 += c[j][2+u];
        }
    }
    s0 += __shfl_xor_sync(~0u, s0, 1); s0 += __shfl_xor_sync(~0u, s0, 2);
    s1 += __shfl_xor_sync(~0u, s1, 1); s1 += __shfl_xor_sync(~0u, s1, 2);
    if (tig == 0) { redsum[wn][wm*16+gid] = s0; redsum[wn][wm*16+gid+8] = s1; }
    __syncthreads();
    float inv0 = 1.f / (redsum[0][wm*16+gid]   + redsum[1][wm*16+gid]);
    float inv1 = 1.f / (redsum[0][wm*16+gid+8] + redsum[1][wm*16+gid+8]);

    size_t orow0 = ((size_t)bh*SS + mrow0) * SS2;
    size_t orow1 = ((size_t)bh*SS + mrow1) * SS2;
    #pragma unroll
    for (int j = 0; j < 32; j++) {
        int cp = wn*128 + j*4 + tig;
        uint32_t hi, lo;
        split2(c[j][0]*inv0, c[j][1]*inv0, hi, lo);
        phi[orow0 + cp] = hi; plo[orow0 + cp] = lo;
        split2(c[j][2]*inv1, c[j][3]*inv1, hi, lo);
        phi[orow1 + cp] = hi; plo[orow1 + cp] = lo;
    }
}

// ---------------------------------------------------------------------------
// PV: attn(packed) = P @ V^T_head; block 128x64, K=512
// ---------------------------------------------------------------------------
__global__ __launch_bounds__(256, 1)
void pv_bf16(const uint32_t* __restrict__ phi, const uint32_t* __restrict__ plo,
             const uint32_t* __restrict__ vthi, const uint32_t* __restrict__ vtlo,
             uint32_t* __restrict__ athi, uint32_t* __restrict__ atlo)
{
    extern __shared__ char smv[];
    const int bh = blockIdx.x, b = bh / NH, hh = bh % NH;
    const int m0 = blockIdx.y * 128;
    const uint32_t* Ah = phi + (size_t)bh*SS*SS2;
    const uint32_t* Al = plo + (size_t)bh*SS*SS2;
    const uint32_t* Bh = vthi + (size_t)bh*DHD*SS2;
    const uint32_t* Bl = vtlo + (size_t)bh*DHD*SS2;
    float c[2][4][4] = {};
    mainloop<2,4,4,2,64>(Ah, Al, SS2, Bh, Bl, SS2, m0, 0, SS, c, smv);

    const int t = threadIdx.x, lane = t & 31, wid = t >> 5;
    const int gid = lane >> 2, tig = lane & 3, wm = wid >> 1, wn = wid & 1;
    #pragma unroll
    for (int i = 0; i < 2; i++) {
        #pragma unroll
        for (int rr = 0; rr < 2; rr++) {
            int m = m0 + wm*32 + i*16 + gid + rr*8;
            #pragma unroll
            for (int j = 0; j < 4; j++) {
                int n = wn*32 + j*8 + tig*2;
                uint32_t hi, lo;
                split2(c[i][j][rr*2 + 0], c[i][j][rr*2 + 1], hi, lo);
                size_t o = (size_t)(b*SS + m)*HID2 + hh*32 + (n>>1);
                athi[o] = hi; atlo[o] = lo;
            }
        }
    }
}

// ---------------------------------------------------------------------------
// Elementwise / small kernels
// ---------------------------------------------------------------------------
__global__ void split_kernel(const float* __restrict__ in,
                             uint32_t* __restrict__ hi, uint32_t* __restrict__ lo) {
    size_t p = ((size_t)blockIdx.x * blockDim.x + threadIdx.x) * 4;
    float4 a = *(const float4*)(in + 2*p);
    float4 b = *(const float4*)(in + 2*p + 4);
    uint32_t h0,l0,h1,l1,h2,l2,h3,l3;
    split2(a.x,a.y,h0,l0); split2(a.z,a.w,h1,l1);
    split2(b.x,b.y,h2,l2); split2(b.z,b.w,h3,l3);
    *(uint4*)(hi + p) = make_uint4(h0,h1,h2,h3);
    *(uint4*)(lo + p) = make_uint4(l0,l1,l2,l3);
}

// interleaved GLU weight split: dest row 2c = gate row c, 2c+1 = up row c
__global__ void glu_split_kernel(const float* __restrict__ gluw,
                                 uint32_t* __restrict__ hi, uint32_t* __restrict__ lo) {
    int idx = blockIdx.x * 256 + threadIdx.x;      // one idx = 4 pairs = 8 floats
    int R = idx / 96;                               // dest row (96 uint4-groups/row)
    int g4 = idx % 96;
    int l = R / (2*INTER), r = R % (2*INTER);
    int srcrow = (r & 1) ? (INTER + (r >> 1)) : (r >> 1);
    const float* src = gluw + ((size_t)l*2*INTER + srcrow)*HID + g4*8;
    float4 a = *(const float4*)(src);
    float4 b = *(const float4*)(src + 4);
    uint32_t h0,l0,h1,l1,h2,l2,h3,l3;
    split2(a.x,a.y,h0,l0); split2(a.z,a.w,h1,l1);
    split2(b.x,b.y,h2,l2); split2(b.z,b.w,h3,l3);
    size_t p = (size_t)R*HID2 + g4*4;
    *(uint4*)(hi + p) = make_uint4(h0,h1,h2,h3);
    *(uint4*)(lo + p) = make_uint4(l0,l1,l2,l3);
}

__global__ void mask_init_kernel(const float* __restrict__ hs, const float* __restrict__ mask,
                                 float* __restrict__ h, uint32_t* __restrict__ hhi,
                                 uint32_t* __restrict__ hlo) {
    size_t p = (size_t)blockIdx.x * 256 + threadIdx.x;
    size_t row = p / HID2;
    float m = mask[row];
    float f0 = hs[2*p] * m, f1 = hs[2*p+1] * m;
    h[2*p] = f0; h[2*p+1] = f1;
    split2(f0, f1, hhi[p], hlo[p]);
}

__global__ void kerple_kernel(const float* __restrict__ r1, const float* __restrict__ r2,
                              const float* __restrict__ r3, int l, float* __restrict__ kb) {
    int rel = threadIdx.x;
    for (int h = 0; h < NH; h++) {
        float c1 = fmaxf(r1[l*NH + h], 1e-7f);
        float c2 = fmaxf(r2[l*NH + h], 1e-7f);
        float c3 = fmaxf(r3[l*NH + h], 1e-7f);
        float v = 0.f;
        if (rel > 0) v = -c1 * log1pf(c2 * powf((float)rel, c3));
        kb[h*SS + rel] = v;
    }
}

// V transpose from packed qkv -> packed vt[bh][d][s-pairs]
__global__ __launch_bounds__(256)
void transpose_v_kernel(const uint32_t* __restrict__ qhi, const uint32_t* __restrict__ qlo,
                        uint32_t* __restrict__ vthi, uint32_t* __restrict__ vtlo) {
    __shared__ float smf[128][65];
    const int bh = blockIdx.x, b = bh / NH, hh = bh % NH;
    const int s0 = blockIdx.y * 128;
    const int t = threadIdx.x;
    const size_t base = (size_t)(b*SS + s0)*QKVN2 + HID + hh*32;  // V at pair-col HID
    #pragma unroll
    for (int it = 0; it < 16; it++) {
        int idx = t + it*256;
        int s = idx >> 5, dp = idx & 31;
        uint32_t hv = qhi[base + (size_t)s*QKVN2 + dp];
        uint32_t lv = qlo[base + (size_t)s*QKVN2 + dp];
        float f0, f1; unpack2(hv, lv, f0, f1);
        smf[s][2*dp] = f0; smf[s][2*dp+1] = f1;
    }
    __syncthreads();
    int d = t & 63, cb = (t >> 6) * 16;
    size_t ob = ((size_t)bh*DHD + d)*SS2 + s0/2 + cb;
    #pragma unroll
    for (int k = 0; k < 16; k++) {
        uint32_t hi, lo;
        split2(smf[2*(cb+k)][d], smf[2*(cb+k)+1][d], hi, lo);
        vthi[ob + k] = hi; vtlo[ob + k] = lo;
    }
}

__global__ __launch_bounds__(384)
void ln_kernel(const float* __restrict__ y, const float* __restrict__ gma,
               const float* __restrict__ bta, const float* __restrict__ mask,
               float* __restrict__ outF, uint32_t* __restrict__ ohi,
               uint32_t* __restrict__ olo) {
    const int row = blockIdx.x;
    const int t = threadIdx.x, w = t >> 5, ln = t & 31;
    const float* py = y + (size_t)row * HID;
    float2 a = *(const float2*)(py + 2*t);

    __shared__ float red[12];
    float s = a.x + a.y;
    #pragma unroll
    for (int o = 16; o; o >>= 1) s += __shfl_xor_sync(~0u, s, o);
    if (ln == 0) red[w] = s;
    __syncthreads();
    float tot = 0.f;
    #pragma unroll
    for (int i = 0; i < 12; i++) tot += red[i];
    float mu = tot * (1.f / HID);
    __syncthreads();

    float d0 = a.x - mu, d1 = a.y - mu;
    float ss = d0*d0 + d1*d1;
    #pragma unroll
    for (int o = 16; o; o >>= 1) ss += __shfl_xor_sync(~0u, ss, o);
    if (ln == 0) red[w] = ss;
    __syncthreads();
    float vtot = 0.f;
    #pragma unroll
    for (int i = 0; i < 12; i++) vtot += red[i];
    float inv = rsqrtf(vtot * (1.f / HID) + 1e-12f);
    float mm = mask[row];

    float o0 = (d0 * inv * gma[2*t]   + bta[2*t])   * mm;
    float o1 = (d1 * inv * gma[2*t+1] + bta[2*t+1]) * mm;
    outF[(size_t)row*HID + 2*t]   = o0;
    outF[(size_t)row*HID + 2*t+1] = o1;
    uint32_t hi, lo; split2(o0, o1, hi, lo);
    ohi[(size_t)row*HID2 + t] = hi;
    olo[(size_t)row*HID2 + t] = lo;
}

// ---------------------------------------------------------------------------
// Launch
// ---------------------------------------------------------------------------
extern "C" void kernel_launch(void* const* d_in, const int* in_sizes, int n_in,
                              void* d_out, int out_size) {
    const float* hs     = (const float*)d_in[0];
    const float* mask   = (const float*)d_in[1];
    const float* Wqkv_w = (const float*)d_in[2];
    const float* Wqkv_b = (const float*)d_in[3];
    const float* aow    = (const float*)d_in[4];
    const float* aob    = (const float*)d_in[5];
    const float* ln1g   = (const float*)d_in[6];
    const float* ln1b   = (const float*)d_in[7];
    const float* gluw   = (const float*)d_in[8];
    const float* wow    = (const float*)d_in[9];
    const float* wob    = (const float*)d_in[10];
    const float* ln2g   = (const float*)d_in[11];
    const float* ln2b   = (const float*)d_in[12];
    const float* r1     = (const float*)d_in[13];
    const float* r2     = (const float*)d_in[14];
    const float* r3     = (const float*)d_in[15];

    float *h, *y, *ao, *kb;
    uint32_t *h_hi,*h_lo,*qkv_hi,*qkv_lo,*p_hi,*p_lo,*vt_hi,*vt_lo,*at_hi,*at_lo;
    uint32_t *ao_hi,*ao_lo,*x_hi,*x_lo;
    uint32_t *wqkv_hi,*wqkv_lo,*wao_hi,*wao_lo,*wglu_hi,*wglu_lo,*wwo_hi,*wwo_lo;
    cudaGetSymbolAddress((void**)&h, g_h);       cudaGetSymbolAddress((void**)&y, g_y);
    cudaGetSymbolAddress((void**)&ao, g_ao);     cudaGetSymbolAddress((void**)&kb, g_kb);
    cudaGetSymbolAddress((void**)&h_hi, g_h_hi);   cudaGetSymbolAddress((void**)&h_lo, g_h_lo);
    cudaGetSymbolAddress((void**)&qkv_hi, g_qkv_hi); cudaGetSymbolAddress((void**)&qkv_lo, g_qkv_lo);
    cudaGetSymbolAddress((void**)&p_hi, g_p_hi);   cudaGetSymbolAddress((void**)&p_lo, g_p_lo);
    cudaGetSymbolAddress((void**)&vt_hi, g_vt_hi); cudaGetSymbolAddress((void**)&vt_lo, g_vt_lo);
    cudaGetSymbolAddress((void**)&at_hi, g_at_hi); cudaGetSymbolAddress((void**)&at_lo, g_at_lo);
    cudaGetSymbolAddress((void**)&ao_hi, g_ao_hi); cudaGetSymbolAddress((void**)&ao_lo, g_ao_lo);
    cudaGetSymbolAddress((void**)&x_hi, g_x_hi);   cudaGetSymbolAddress((void**)&x_lo, g_x_lo);
    cudaGetSymbolAddress((void**)&wqkv_hi, g_wqkv_hi); cudaGetSymbolAddress((void**)&wqkv_lo, g_wqkv_lo);
    cudaGetSymbolAddress((void**)&wao_hi, g_wao_hi);   cudaGetSymbolAddress((void**)&wao_lo, g_wao_lo);
    cudaGetSymbolAddress((void**)&wglu_hi, g_wglu_hi); cudaGetSymbolAddress((void**)&wglu_lo, g_wglu_lo);
    cudaGetSymbolAddress((void**)&wwo_hi, g_wwo_hi);   cudaGetSymbolAddress((void**)&wwo_lo, g_wwo_lo);

    cudaFuncSetAttribute(gemm_bf16, cudaFuncAttributeMaxDynamicSharedMemorySize, 98304);
    cudaFuncSetAttribute(gemm_glu,  cudaFuncAttributeMaxDynamicSharedMemorySize, 98304);
    cudaFuncSetAttribute(pv_bf16,   cudaFuncAttributeMaxDynamicSharedMemorySize, 73728);
    cudaFuncSetAttribute(attn_scores_softmax, cudaFuncAttributeMaxDynamicSharedMemorySize, 147456);

    // weight splits (per call; deterministic)
    split_kernel<<<LAY*QKVN*HID/8/256, 256>>>(Wqkv_w, wqkv_hi, wqkv_lo);
    split_kernel<<<LAY*HID*HID/8/256, 256>>>(aow, wao_hi, wao_lo);
    glu_split_kernel<<<(int)((size_t)LAY*2*INTER*96/256), 256>>>(gluw, wglu_hi, wglu_lo);
    split_kernel<<<(int)((size_t)LAY*HID*INTER/8/256), 256>>>(wow, wwo_hi, wwo_lo);

    mask_init_kernel<<<TOK*HID2/256, 256>>>(hs, mask, h, h_hi, h_lo);

    for (int l = 0; l < LAY; l++) {
        kerple_kernel<<<1, SS>>>(r1, r2, r3, l, kb);

        // qkv (packed only)
        gemm_bf16<<<dim3(QKVN/128, TOK/128), 256, 98304>>>(
            h_hi, h_lo, wqkv_hi + (size_t)l*QKVN*HID/2, wqkv_lo + (size_t)l*QKVN*HID/2,
            Wqkv_b + (size_t)l*QKVN, nullptr, mask, nullptr, qkv_hi, qkv_lo,
            TOK, QKVN, HID);

        transpose_v_kernel<<<dim3(BNH, SS/128), 256>>>(qkv_hi, qkv_lo, vt_hi, vt_lo);
        attn_scores_softmax<<<dim3(SS/64, BNH), 256, 147456>>>(qkv_hi, qkv_lo, mask, kb, p_hi, p_lo);
        pv_bf16<<<dim3(BNH, SS/128), 256, 73728>>>(p_hi, p_lo, vt_hi, vt_lo, at_hi, at_lo);

        gemm_bf16<<<dim3(HID/128, TOK/128), 256, 98304>>>(
            at_hi, at_lo, wao_hi + (size_t)l*HID*HID/2, wao_lo + (size_t)l*HID*HID/2,
            aob + (size_t)l*HID, h, nullptr, y, nullptr, nullptr,
            TOK, HID, HID);
        ln_kernel<<<TOK, 384>>>(y, ln1g + (size_t)l*HID, ln1b + (size_t)l*HID, mask,
                                ao, ao_hi, ao_lo);

        // GLU + gelu*mul fused
        gemm_glu<<<dim3(2*INTER/128, TOK/128), 256, 98304>>>(
            ao_hi, ao_lo, wglu_hi + (size_t)l*2*INTER*HID/2, wglu_lo + (size_t)l*2*INTER*HID/2,
            x_hi, x_lo, HID);

        gemm_bf16<<<dim3(HID/128, TOK/128), 256, 98304>>>(
            x_hi, x_lo, wwo_hi + (size_t)l*HID*INTER/2, wwo_lo + (size_t)l*HID*INTER/2,
            wob + (size_t)l*HID, ao, nullptr, y, nullptr, nullptr,
            TOK, HID, INTER);

        float* hout = (l == LAY-1) ? (float*)d_out : h;
        ln_kernel<<<TOK, 384>>>(y, ln2g + (size_t)l*HID, ln2b + (size_t)l*HID, mask,
                                hout, h_hi, h_lo);
    }
}

// round 5
// speedup vs baseline: 2.5773x; 1.0572x over previous
#include <cuda_runtime.h>
#include <cuda_bf16.h>
#include <math.h>
#include <stdint.h>

#define BB 8
#define SS 512
#define HID 768
#define NH 12
#define DHD 64
#define INTER 3072
#define LAY 4
#define TOK (BB*SS)
#define QKVN (3*HID)
#define BNH (BB*NH)
#define HID2 (HID/2)
#define QKVN2 (QKVN/2)
#define INTER2 (INTER/2)
#define SS2 (SS/2)

// ---------------------------------------------------------------------------
// Scratch
// ---------------------------------------------------------------------------
__device__ float g_h  [TOK*HID];
__device__ float g_y  [TOK*HID];
__device__ float g_ao [TOK*HID];
__device__ float g_kb [LAY*NH*SS];

__device__ uint32_t g_h_hi [TOK*HID2],  g_h_lo [TOK*HID2];
__device__ uint32_t g_qkv_hi[TOK*QKVN2], g_qkv_lo[TOK*QKVN2];
__device__ uint32_t g_p_hi [(size_t)BNH*SS*SS2], g_p_lo [(size_t)BNH*SS*SS2];
__device__ uint32_t g_vt_hi[BNH*DHD*SS2], g_vt_lo[BNH*DHD*SS2];
__device__ uint32_t g_at_hi[TOK*HID2],  g_at_lo[TOK*HID2];
__device__ uint32_t g_ao_hi[TOK*HID2],  g_ao_lo[TOK*HID2];
__device__ uint32_t g_x_hi [(size_t)TOK*INTER2], g_x_lo [(size_t)TOK*INTER2];

__device__ uint32_t g_wqkv_hi[LAY*QKVN*HID/2], g_wqkv_lo[LAY*QKVN*HID/2];
__device__ uint32_t g_wao_hi [LAY*HID*HID/2],  g_wao_lo [LAY*HID*HID/2];
__device__ uint32_t g_wglu_hi[(size_t)LAY*2*INTER*HID/2], g_wglu_lo[(size_t)LAY*2*INTER*HID/2];
__device__ uint32_t g_wwo_hi [(size_t)LAY*HID*INTER/2],  g_wwo_lo [(size_t)LAY*HID*INTER/2];

// ---------------------------------------------------------------------------
// Helpers
// ---------------------------------------------------------------------------
__device__ __forceinline__ void split2(float f0, float f1, uint32_t& hi, uint32_t& lo) {
    __nv_bfloat16 h0 = __float2bfloat16_rn(f0);
    __nv_bfloat16 h1 = __float2bfloat16_rn(f1);
    float r0 = f0 - __bfloat162float(h0);
    float r1 = f1 - __bfloat162float(h1);
    __nv_bfloat16 l0 = __float2bfloat16_rn(r0);
    __nv_bfloat16 l1 = __float2bfloat16_rn(r1);
    hi = ((uint32_t)__bfloat16_as_ushort(h1) << 16) | (uint32_t)__bfloat16_as_ushort(h0);
    lo = ((uint32_t)__bfloat16_as_ushort(l1) << 16) | (uint32_t)__bfloat16_as_ushort(l0);
}

__device__ __forceinline__ void unpack2(uint32_t hi, uint32_t lo, float& f0, float& f1) {
    f0 = __bfloat162float(__ushort_as_bfloat16((unsigned short)(hi & 0xffff)))
       + __bfloat162float(__ushort_as_bfloat16((unsigned short)(lo & 0xffff)));
    f1 = __bfloat162float(__ushort_as_bfloat16((unsigned short)(hi >> 16)))
       + __bfloat162float(__ushort_as_bfloat16((unsigned short)(lo >> 16)));
}

__device__ __forceinline__ void mma16(float* c, const uint32_t* a, const uint32_t* b) {
    asm volatile(
        "mma.sync.aligned.m16n8k16.row.col.f32.bf16.bf16.f32 "
        "{%0,%1,%2,%3}, {%4,%5,%6,%7}, {%8,%9}, {%0,%1,%2,%3};"
        : "+f"(c[0]), "+f"(c[1]), "+f"(c[2]), "+f"(c[3])
        : "r"(a[0]), "r"(a[1]), "r"(a[2]), "r"(a[3]), "r"(b[0]), "r"(b[1]));
}

__device__ __forceinline__ void ldsm4(uint32_t* r, uint32_t saddr) {
    asm volatile("ldmatrix.sync.aligned.m8n8.x4.shared.b16 {%0,%1,%2,%3}, [%4];"
        : "=r"(r[0]), "=r"(r[1]), "=r"(r[2]), "=r"(r[3]) : "r"(saddr));
}

__device__ __forceinline__ void cp16s(uint32_t saddr, const void* g) {
    asm volatile("cp.async.ca.shared.global [%0], [%1], 16;" :: "r"(saddr), "l"(g));
}

__device__ __forceinline__ int swz(int row, int ch) {
    return row * 64 + ((ch ^ ((row >> 1) & 3)) << 4);
}

// ---------------------------------------------------------------------------
// BF16x3 mainloop (unchanged — proven)
// ---------------------------------------------------------------------------
template<int IT, int JT, int WM, int WN, int BROWS>
__device__ __forceinline__ void mainloop(
    const uint32_t* __restrict__ Ahi, const uint32_t* __restrict__ Alo, int lda2,
    const uint32_t* __restrict__ Bhi, const uint32_t* __restrict__ Blo, int ldb2,
    int m0, int n0, int K, float (*c)[JT][4], char* smptr)
{
    constexpr int ASZ = 128 * 64;
    constexpr int BSZ = BROWS * 64;
    constexpr int STG = 2 * ASZ + 2 * BSZ;
    constexpr int BITER = (BROWS * 4) / 256;
    const int t = threadIdx.x, lane = t & 31, wid = t >> 5;
    const int wm = wid / WN, wn = wid % WN;
    const uint32_t sbase = (uint32_t)__cvta_generic_to_shared(smptr);
    const int KT = K >> 5;

    auto prefetch = [&](int st, int k0) {
        int kc = k0 >> 1;
        uint32_t s0 = sbase + st * STG;
        #pragma unroll
        for (int it2 = 0; it2 < 2; it2++) {
            int idx = t + it2 * 256; int row = idx >> 2, ch = idx & 3;
            int so = swz(row, ch);
            size_t go = (size_t)(m0 + row) * lda2 + kc + ch * 4;
            cp16s(s0 + so, Ahi + go);
            cp16s(s0 + ASZ + so, Alo + go);
        }
        #pragma unroll
        for (int it2 = 0; it2 < BITER; it2++) {
            int idx = t + it2 * 256; int row = idx >> 2, ch = idx & 3;
            int so = swz(row, ch);
            size_t go = (size_t)(n0 + row) * ldb2 + kc + ch * 4;
            cp16s(s0 + 2 * ASZ + so, Bhi + go);
            cp16s(s0 + 2 * ASZ + BSZ + so, Blo + go);
        }
        asm volatile("cp.async.commit_group;");
    };

    prefetch(0, 0);
    if (KT > 1) prefetch(1, 32);

    for (int kt = 0; kt < KT; kt++) {
        int st = kt % 3;
        if (kt + 2 < KT)      { prefetch((kt + 2) % 3, (kt + 2) * 32);
                                asm volatile("cp.async.wait_group 2;"); }
        else if (kt + 1 < KT) { asm volatile("cp.async.wait_group 1;"); }
        else                  { asm volatile("cp.async.wait_group 0;"); }
        __syncthreads();

        uint32_t aH = sbase + st * STG, aL = aH + ASZ;
        uint32_t bH = aH + 2 * ASZ,     bL = bH + BSZ;

        #pragma unroll
        for (int s = 0; s < 2; s++) {
            const int arow = wm * IT * 16 + (lane & 15);
            const int ach  = s * 2 + (lane >> 4);
            const int brow = wn * JT * 8 + (lane & 7) + ((lane >> 4) << 3);
            const int bch  = s * 2 + ((lane >> 3) & 1);

            uint32_t ah[IT][4], bh_[JT][2];
            #pragma unroll
            for (int i = 0; i < IT; i++)
                ldsm4(ah[i], aH + swz(arow + i * 16, ach));
            #pragma unroll
            for (int jp = 0; jp < JT / 2; jp++) {
                uint32_t rg[4];
                ldsm4(rg, bH + swz(brow + jp * 16, bch));
                bh_[jp*2][0] = rg[0]; bh_[jp*2][1] = rg[1];
                bh_[jp*2+1][0] = rg[2]; bh_[jp*2+1][1] = rg[3];
            }
            #pragma unroll
            for (int i = 0; i < IT; i++)
                #pragma unroll
                for (int j = 0; j < JT; j++)
                    mma16(c[i][j], ah[i], bh_[j]);
            uint32_t bl_[JT][2];
            #pragma unroll
            for (int jp = 0; jp < JT / 2; jp++) {
                uint32_t rg[4];
                ldsm4(rg, bL + swz(brow + jp * 16, bch));
                bl_[jp*2][0] = rg[0]; bl_[jp*2][1] = rg[1];
                bl_[jp*2+1][0] = rg[2]; bl_[jp*2+1][1] = rg[3];
            }
            #pragma unroll
            for (int i = 0; i < IT; i++)
                #pragma unroll
                for (int j = 0; j < JT; j++)
                    mma16(c[i][j], ah[i], bl_[j]);
            uint32_t al[IT][4];
            #pragma unroll
            for (int i = 0; i < IT; i++)
                ldsm4(al[i], aL + swz(arow + i * 16, ach));
            #pragma unroll
            for (int i = 0; i < IT; i++)
                #pragma unroll
                for (int j = 0; j < JT; j++)
                    mma16(c[i][j], al[i], bh_[j]);
        }
        __syncthreads();
    }
}

// ---------------------------------------------------------------------------
// Generic GEMM (128x128): 2 CTAs/SM for issue overlap
// ---------------------------------------------------------------------------
__global__ __launch_bounds__(256, 2)
void gemm_bf16(const uint32_t* __restrict__ Ahi, const uint32_t* __restrict__ Alo,
               const uint32_t* __restrict__ Whi, const uint32_t* __restrict__ Wlo,
               const float* __restrict__ bias, const float* __restrict__ res,
               const float* __restrict__ mask,
               float* __restrict__ outF, uint32_t* __restrict__ outHi,
               uint32_t* __restrict__ outLo, int M, int N, int K)
{
    extern __shared__ char smv[];
    float c[4][4][4] = {};
    const int m0 = blockIdx.y * 128, n0 = blockIdx.x * 128;
    mainloop<4,4,2,4,128>(Ahi, Alo, K/2, Whi, Wlo, K/2, m0, n0, K, c, smv);

    const int t = threadIdx.x, lane = t & 31, wid = t >> 5;
    const int gid = lane >> 2, tig = lane & 3, wm = wid >> 2, wn = wid & 3;
    const int N2 = N >> 1;
    #pragma unroll
    for (int i = 0; i < 4; i++) {
        #pragma unroll
        for (int rr = 0; rr < 2; rr++) {
            int m = m0 + wm*64 + i*16 + gid + rr*8;
            float mm = mask ? mask[m] : 1.f;
            #pragma unroll
            for (int j = 0; j < 4; j++) {
                int n = n0 + wn*32 + j*8 + tig*2;
                float v0 = c[i][j][rr*2 + 0], v1 = c[i][j][rr*2 + 1];
                if (bias) { v0 += bias[n]; v1 += bias[n+1]; }
                if (res)  { v0 += res[(size_t)m*N + n]; v1 += res[(size_t)m*N + n+1]; }
                v0 *= mm; v1 *= mm;
                if (outF) { outF[(size_t)m*N + n] = v0; outF[(size_t)m*N + n+1] = v1; }
                if (outHi) {
                    uint32_t hi, lo; split2(v0, v1, hi, lo);
                    outHi[(size_t)m*N2 + (n>>1)] = hi;
                    outLo[(size_t)m*N2 + (n>>1)] = lo;
                }
            }
        }
    }
}

// ---------------------------------------------------------------------------
// GLU GEMM: g = ao @ glu_w_interleaved^T; epilogue x = gelu(gate)*up, packed out
// ---------------------------------------------------------------------------
__global__ __launch_bounds__(256, 2)
void gemm_glu(const uint32_t* __restrict__ Ahi, const uint32_t* __restrict__ Alo,
              const uint32_t* __restrict__ Whi, const uint32_t* __restrict__ Wlo,
              uint32_t* __restrict__ xhi, uint32_t* __restrict__ xlo, int K)
{
    extern __shared__ char smv[];
    float c[4][4][4] = {};
    const int m0 = blockIdx.y * 128, n0 = blockIdx.x * 128;
    mainloop<4,4,2,4,128>(Ahi, Alo, K/2, Whi, Wlo, K/2, m0, n0, K, c, smv);

    const int t = threadIdx.x, lane = t & 31, wid = t >> 5;
    const int gid = lane >> 2, tig = lane & 3, wm = wid >> 2, wn = wid & 3;
    #pragma unroll
    for (int i = 0; i < 4; i++) {
        #pragma unroll
        for (int rr = 0; rr < 2; rr++) {
            int m = m0 + wm*64 + i*16 + gid + rr*8;
            #pragma unroll
            for (int j = 0; j < 4; j++) {
                float v0 = c[i][j][rr*2 + 0], v1 = c[i][j][rr*2 + 1];
                float x = 0.5f * v0 * (1.f + erff(v0 * 0.70710678118654752f)) * v1;
                float xo = __shfl_xor_sync(0xffffffffu, x, 1);
                if (!(tig & 1)) {
                    uint32_t hi, lo; split2(x, xo, hi, lo);
                    size_t o = (size_t)m*INTER2 + (n0>>2) + wn*8 + j*2 + (tig>>1);
                    xhi[o] = hi; xlo[o] = lo;
                }
            }
        }
    }
}

// ---------------------------------------------------------------------------
// Fused scores + bias + softmax (unchanged)
// ---------------------------------------------------------------------------
__global__ __launch_bounds__(256, 1)
void attn_scores_softmax(const uint32_t* __restrict__ qhi, const uint32_t* __restrict__ qlo,
                         const float* __restrict__ mask, const float* __restrict__ kb,
                         uint32_t* __restrict__ phi, uint32_t* __restrict__ plo)
{
    extern __shared__ char smv[];
    __shared__ float mask_s[SS], kb_s[SS];
    __shared__ float redmax[2][64], redsum[2][64];

    const int bh = blockIdx.y, b = bh / NH, hh = bh % NH;
    const int m0 = blockIdx.x * 64;
    const int t = threadIdx.x, lane = t & 31, wid = t >> 5;
    const int gid = lane >> 2, tig = lane & 3;
    const int wm = wid >> 1, wn = wid & 1;

    const uint32_t sb = (uint32_t)__cvta_generic_to_shared(smv);
    const uint32_t sQH = sb, sQL = sb + 8192, sKH = sb + 16384, sKL = sb + 81920;

    const uint32_t* Qh = qhi + (size_t)b*SS*QKVN2 + hh*32;
    const uint32_t* Ql = qlo + (size_t)b*SS*QKVN2 + hh*32;
    const uint32_t* Kh = Qh + HID2;
    const uint32_t* Kl = Ql + HID2;

    #pragma unroll
    for (int it = 0; it < 2; it++) {
        int idx = t + it*256, row = idx >> 3, chunk = (idx >> 2) & 1, ch = idx & 3;
        size_t go = (size_t)(m0 + row)*QKVN2 + chunk*16 + ch*4;
        int so = chunk*4096 + swz(row, ch);
        cp16s(sQH + so, Qh + go);
        cp16s(sQL + so, Ql + go);
    }
    #pragma unroll
    for (int it = 0; it < 16; it++) {
        int idx = t + it*256, row = idx >> 3, chunk = (idx >> 2) & 1, ch = idx & 3;
        size_t go = (size_t)row*QKVN2 + chunk*16 + ch*4;
        int so = chunk*32768 + swz(row, ch);
        cp16s(sKH + so, Kh + go);
        cp16s(sKL + so, Kl + go);
    }
    {
        uint32_t ms = (uint32_t)__cvta_generic_to_shared(mask_s);
        uint32_t ks = (uint32_t)__cvta_generic_to_shared(kb_s);
        if (t < 128) cp16s(ms + t*16, mask + b*SS + t*4);
        else         cp16s(ks + (t-128)*16, kb + hh*SS + (t-128)*4);
    }
    asm volatile("cp.async.commit_group;");
    asm volatile("cp.async.wait_group 0;");
    __syncthreads();

    float c[32][4] = {};
    #pragma unroll
    for (int s4 = 0; s4 < 4; s4++) {
        int chunk = s4 >> 1, ss_ = s4 & 1;
        int arow = wm*16 + (lane & 15);
        int ach = ss_*2 + (lane >> 4);
        uint32_t ah[4], al[4];
        ldsm4(ah, sQH + chunk*4096 + swz(arow, ach));
        ldsm4(al, sQL + chunk*4096 + swz(arow, ach));
        int browb = wn*256 + (lane & 7) + ((lane >> 4) << 3);
        int bch = ss_*2 + ((lane >> 3) & 1);
        #pragma unroll
        for (int jp = 0; jp < 16; jp++) {
            uint32_t bh_[4], bl_[4];
            ldsm4(bh_, sKH + chunk*32768 + swz(browb + jp*16, bch));
            ldsm4(bl_, sKL + chunk*32768 + swz(browb + jp*16, bch));
            mma16(c[2*jp],   ah, bh_);
            mma16(c[2*jp+1], ah, bh_ + 2);
            mma16(c[2*jp],   ah, bl_);
            mma16(c[2*jp+1], ah, bl_ + 2);
            mma16(c[2*jp],   al, bh_);
            mma16(c[2*jp+1], al, bh_ + 2);
        }
    }

    const int mrow0 = m0 + wm*16 + gid, mrow1 = mrow0 + 8;
    float mx0 = -1e30f, mx1 = -1e30f;
    #pragma unroll
    for (int j = 0; j < 32; j++) {
        int n = wn*256 + j*8 + tig*2;
        #pragma unroll
        for (int u = 0; u < 2; u++) {
            int nn = n + u;
            float badd = (mask_s[nn] - 1.f) * 10000.f;
            int r0 = mrow0 > nn ? mrow0 - nn : nn - mrow0;
            int r1 = mrow1 > nn ? mrow1 - nn : nn - mrow1;
            c[j][u]   = c[j][u]   * 0.125f + kb_s[r0] + badd;
            c[j][2+u] = c[j][2+u] * 0.125f + kb_s[r1] + badd;
            mx0 = fmaxf(mx0, c[j][u]);
            mx1 = fmaxf(mx1, c[j][2+u]);
        }
    }
    mx0 = fmaxf(mx0, __shfl_xor_sync(~0u, mx0, 1));
    mx0 = fmaxf(mx0, __shfl_xor_sync(~0u, mx0, 2));
    mx1 = fmaxf(mx1, __shfl_xor_sync(~0u, mx1, 1));
    mx1 = fmaxf(mx1, __shfl_xor_sync(~0u, mx1, 2));
    if (tig == 0) { redmax[wn][wm*16+gid] = mx0; redmax[wn][wm*16+gid+8] = mx1; }
    __syncthreads();
    mx0 = fmaxf(redmax[0][wm*16+gid],   redmax[1][wm*16+gid]);
    mx1 = fmaxf(redmax[0][wm*16+gid+8], redmax[1][wm*16+gid+8]);

    float s0 = 0.f, s1 = 0.f;
    #pragma unroll
    for (int j = 0; j < 32; j++) {
        #pragma unroll
        for (int u = 0; u < 2; u++) {
            c[j][u]   = __expf(c[j][u]   - mx0); s0 += c[j][u];
            c[j][2+u] = __expf(c[j][2+u] - mx1); s1 += c[j][2+u];
        }
    }
    s0 += __shfl_xor_sync(~0u, s0, 1); s0 += __shfl_xor_sync(~0u, s0, 2);
    s1 += __shfl_xor_sync(~0u, s1, 1); s1 += __shfl_xor_sync(~0u, s1, 2);
    if (tig == 0) { redsum[wn][wm*16+gid] = s0; redsum[wn][wm*16+gid+8] = s1; }
    __syncthreads();
    float inv0 = 1.f / (redsum[0][wm*16+gid]   + redsum[1][wm*16+gid]);
    float inv1 = 1.f / (redsum[0][wm*16+gid+8] + redsum[1][wm*16+gid+8]);

    size_t orow0 = ((size_t)bh*SS + mrow0) * SS2;
    size_t orow1 = ((size_t)bh*SS + mrow1) * SS2;
    #pragma unroll
    for (int j = 0; j < 32; j++) {
        int cp = wn*128 + j*4 + tig;
        uint32_t hi, lo;
        split2(c[j][0]*inv0, c[j][1]*inv0, hi, lo);
        phi[orow0 + cp] = hi; plo[orow0 + cp] = lo;
        split2(c[j][2]*inv1, c[j][3]*inv1, hi, lo);
        phi[orow1 + cp] = hi; plo[orow1 + cp] = lo;
    }
}

// ---------------------------------------------------------------------------
// PV: attn(packed) = P @ V^T_head; 2 CTAs/SM
// ---------------------------------------------------------------------------
__global__ __launch_bounds__(256, 2)
void pv_bf16(const uint32_t* __restrict__ phi, const uint32_t* __restrict__ plo,
             const uint32_t* __restrict__ vthi, const uint32_t* __restrict__ vtlo,
             uint32_t* __restrict__ athi, uint32_t* __restrict__ atlo)
{
    extern __shared__ char smv[];
    const int bh = blockIdx.x, b = bh / NH, hh = bh % NH;
    const int m0 = blockIdx.y * 128;
    const uint32_t* Ah = phi + (size_t)bh*SS*SS2;
    const uint32_t* Al = plo + (size_t)bh*SS*SS2;
    const uint32_t* Bh = vthi + (size_t)bh*DHD*SS2;
    const uint32_t* Bl = vtlo + (size_t)bh*DHD*SS2;
    float c[2][4][4] = {};
    mainloop<2,4,4,2,64>(Ah, Al, SS2, Bh, Bl, SS2, m0, 0, SS, c, smv);

    const int t = threadIdx.x, lane = t & 31, wid = t >> 5;
    const int gid = lane >> 2, tig = lane & 3, wm = wid >> 1, wn = wid & 1;
    #pragma unroll
    for (int i = 0; i < 2; i++) {
        #pragma unroll
        for (int rr = 0; rr < 2; rr++) {
            int m = m0 + wm*32 + i*16 + gid + rr*8;
            #pragma unroll
            for (int j = 0; j < 4; j++) {
                int n = wn*32 + j*8 + tig*2;
                uint32_t hi, lo;
                split2(c[i][j][rr*2 + 0], c[i][j][rr*2 + 1], hi, lo);
                size_t o = (size_t)(b*SS + m)*HID2 + hh*32 + (n>>1);
                athi[o] = hi; atlo[o] = lo;
            }
        }
    }
}

// ---------------------------------------------------------------------------
// Elementwise / small kernels
// ---------------------------------------------------------------------------
__global__ void split_kernel(const float* __restrict__ in,
                             uint32_t* __restrict__ hi, uint32_t* __restrict__ lo) {
    size_t p = ((size_t)blockIdx.x * blockDim.x + threadIdx.x) * 4;
    float4 a = *(const float4*)(in + 2*p);
    float4 b = *(const float4*)(in + 2*p + 4);
    uint32_t h0,l0,h1,l1,h2,l2,h3,l3;
    split2(a.x,a.y,h0,l0); split2(a.z,a.w,h1,l1);
    split2(b.x,b.y,h2,l2); split2(b.z,b.w,h3,l3);
    *(uint4*)(hi + p) = make_uint4(h0,h1,h2,h3);
    *(uint4*)(lo + p) = make_uint4(l0,l1,l2,l3);
}

__global__ void glu_split_kernel(const float* __restrict__ gluw,
                                 uint32_t* __restrict__ hi, uint32_t* __restrict__ lo) {
    int idx = blockIdx.x * 256 + threadIdx.x;
    int R = idx / 96;
    int g4 = idx % 96;
    int l = R / (2*INTER), r = R % (2*INTER);
    int srcrow = (r & 1) ? (INTER + (r >> 1)) : (r >> 1);
    const float* src = gluw + ((size_t)l*2*INTER + srcrow)*HID + g4*8;
    float4 a = *(const float4*)(src);
    float4 b = *(const float4*)(src + 4);
    uint32_t h0,l0,h1,l1,h2,l2,h3,l3;
    split2(a.x,a.y,h0,l0); split2(a.z,a.w,h1,l1);
    split2(b.x,b.y,h2,l2); split2(b.z,b.w,h3,l3);
    size_t p = (size_t)R*HID2 + g4*4;
    *(uint4*)(hi + p) = make_uint4(h0,h1,h2,h3);
    *(uint4*)(lo + p) = make_uint4(l0,l1,l2,l3);
}

__global__ void mask_init_kernel(const float* __restrict__ hs, const float* __restrict__ mask,
                                 float* __restrict__ h, uint32_t* __restrict__ hhi,
                                 uint32_t* __restrict__ hlo) {
    size_t p = (size_t)blockIdx.x * 256 + threadIdx.x;
    size_t row = p / HID2;
    float m = mask[row];
    float f0 = hs[2*p] * m, f1 = hs[2*p+1] * m;
    h[2*p] = f0; h[2*p+1] = f1;
    split2(f0, f1, hhi[p], hlo[p]);
}

// all layers at once
__global__ void kerple_kernel(const float* __restrict__ r1, const float* __restrict__ r2,
                              const float* __restrict__ r3, float* __restrict__ kb) {
    int rel = threadIdx.x;
    int l = blockIdx.x;
    for (int h = 0; h < NH; h++) {
        float c1 = fmaxf(r1[l*NH + h], 1e-7f);
        float c2 = fmaxf(r2[l*NH + h], 1e-7f);
        float c3 = fmaxf(r3[l*NH + h], 1e-7f);
        float v = 0.f;
        if (rel > 0) v = -c1 * log1pf(c2 * powf((float)rel, c3));
        kb[(l*NH + h)*SS + rel] = v;
    }
}

__global__ __launch_bounds__(256)
void transpose_v_kernel(const uint32_t* __restrict__ qhi, const uint32_t* __restrict__ qlo,
                        uint32_t* __restrict__ vthi, uint32_t* __restrict__ vtlo) {
    __shared__ float smf[128][65];
    const int bh = blockIdx.x, b = bh / NH, hh = bh % NH;
    const int s0 = blockIdx.y * 128;
    const int t = threadIdx.x;
    const size_t base = (size_t)(b*SS + s0)*QKVN2 + HID + hh*32;
    #pragma unroll
    for (int it = 0; it < 16; it++) {
        int idx = t + it*256;
        int s = idx >> 5, dp = idx & 31;
        uint32_t hv = qhi[base + (size_t)s*QKVN2 + dp];
        uint32_t lv = qlo[base + (size_t)s*QKVN2 + dp];
        float f0, f1; unpack2(hv, lv, f0, f1);
        smf[s][2*dp] = f0; smf[s][2*dp+1] = f1;
    }
    __syncthreads();
    int d = t & 63, cb = (t >> 6) * 16;
    size_t ob = ((size_t)bh*DHD + d)*SS2 + s0/2 + cb;
    #pragma unroll
    for (int k = 0; k < 16; k++) {
        uint32_t hi, lo;
        split2(smf[2*(cb+k)][d], smf[2*(cb+k)+1][d], hi, lo);
        vthi[ob + k] = hi; vtlo[ob + k] = lo;
    }
}

__global__ __launch_bounds__(384)
void ln_kernel(const float* __restrict__ y, const float* __restrict__ gma,
               const float* __restrict__ bta, const float* __restrict__ mask,
               float* __restrict__ outF, uint32_t* __restrict__ ohi,
               uint32_t* __restrict__ olo) {
    const int row = blockIdx.x;
    const int t = threadIdx.x, w = t >> 5, ln = t & 31;
    const float* py = y + (size_t)row * HID;
    float2 a = *(const float2*)(py + 2*t);

    __shared__ float red[12];
    float s = a.x + a.y;
    #pragma unroll
    for (int o = 16; o; o >>= 1) s += __shfl_xor_sync(~0u, s, o);
    if (ln == 0) red[w] = s;
    __syncthreads();
    float tot = 0.f;
    #pragma unroll
    for (int i = 0; i < 12; i++) tot += red[i];
    float mu = tot * (1.f / HID);
    __syncthreads();

    float d0 = a.x - mu, d1 = a.y - mu;
    float ss = d0*d0 + d1*d1;
    #pragma unroll
    for (int o = 16; o; o >>= 1) ss += __shfl_xor_sync(~0u, ss, o);
    if (ln == 0) red[w] = ss;
    __syncthreads();
    float vtot = 0.f;
    #pragma unroll
    for (int i = 0; i < 12; i++) vtot += red[i];
    float inv = rsqrtf(vtot * (1.f / HID) + 1e-12f);
    float mm = mask[row];

    float o0 = (d0 * inv * gma[2*t]   + bta[2*t])   * mm;
    float o1 = (d1 * inv * gma[2*t+1] + bta[2*t+1]) * mm;
    outF[(size_t)row*HID + 2*t]   = o0;
    outF[(size_t)row*HID + 2*t+1] = o1;
    uint32_t hi, lo; split2(o0, o1, hi, lo);
    ohi[(size_t)row*HID2 + t] = hi;
    olo[(size_t)row*HID2 + t] = lo;
}

// ---------------------------------------------------------------------------
// Launch
// ---------------------------------------------------------------------------
extern "C" void kernel_launch(void* const* d_in, const int* in_sizes, int n_in,
                              void* d_out, int out_size) {
    const float* hs     = (const float*)d_in[0];
    const float* mask   = (const float*)d_in[1];
    const float* Wqkv_w = (const float*)d_in[2];
    const float* Wqkv_b = (const float*)d_in[3];
    const float* aow    = (const float*)d_in[4];
    const float* aob    = (const float*)d_in[5];
    const float* ln1g   = (const float*)d_in[6];
    const float* ln1b   = (const float*)d_in[7];
    const float* gluw   = (const float*)d_in[8];
    const float* wow    = (const float*)d_in[9];
    const float* wob    = (const float*)d_in[10];
    const float* ln2g   = (const float*)d_in[11];
    const float* ln2b   = (const float*)d_in[12];
    const float* r1     = (const float*)d_in[13];
    const float* r2     = (const float*)d_in[14];
    const float* r3     = (const float*)d_in[15];

    float *h, *y, *ao, *kb;
    uint32_t *h_hi,*h_lo,*qkv_hi,*qkv_lo,*p_hi,*p_lo,*vt_hi,*vt_lo,*at_hi,*at_lo;
    uint32_t *ao_hi,*ao_lo,*x_hi,*x_lo;
    uint32_t *wqkv_hi,*wqkv_lo,*wao_hi,*wao_lo,*wglu_hi,*wglu_lo,*wwo_hi,*wwo_lo;
    cudaGetSymbolAddress((void**)&h, g_h);       cudaGetSymbolAddress((void**)&y, g_y);
    cudaGetSymbolAddress((void**)&ao, g_ao);     cudaGetSymbolAddress((void**)&kb, g_kb);
    cudaGetSymbolAddress((void**)&h_hi, g_h_hi);   cudaGetSymbolAddress((void**)&h_lo, g_h_lo);
    cudaGetSymbolAddress((void**)&qkv_hi, g_qkv_hi); cudaGetSymbolAddress((void**)&qkv_lo, g_qkv_lo);
    cudaGetSymbolAddress((void**)&p_hi, g_p_hi);   cudaGetSymbolAddress((void**)&p_lo, g_p_lo);
    cudaGetSymbolAddress((void**)&vt_hi, g_vt_hi); cudaGetSymbolAddress((void**)&vt_lo, g_vt_lo);
    cudaGetSymbolAddress((void**)&at_hi, g_at_hi); cudaGetSymbolAddress((void**)&at_lo, g_at_lo);
    cudaGetSymbolAddress((void**)&ao_hi, g_ao_hi); cudaGetSymbolAddress((void**)&ao_lo, g_ao_lo);
    cudaGetSymbolAddress((void**)&x_hi, g_x_hi);   cudaGetSymbolAddress((void**)&x_lo, g_x_lo);
    cudaGetSymbolAddress((void**)&wqkv_hi, g_wqkv_hi); cudaGetSymbolAddress((void**)&wqkv_lo, g_wqkv_lo);
    cudaGetSymbolAddress((void**)&wao_hi, g_wao_hi);   cudaGetSymbolAddress((void**)&wao_lo, g_wao_lo);
    cudaGetSymbolAddress((void**)&wglu_hi, g_wglu_hi); cudaGetSymbolAddress((void**)&wglu_lo, g_wglu_lo);
    cudaGetSymbolAddress((void**)&wwo_hi, g_wwo_hi);   cudaGetSymbolAddress((void**)&wwo_lo, g_wwo_lo);

    cudaFuncSetAttribute(gemm_bf16, cudaFuncAttributeMaxDynamicSharedMemorySize, 98304);
    cudaFuncSetAttribute(gemm_glu,  cudaFuncAttributeMaxDynamicSharedMemorySize, 98304);
    cudaFuncSetAttribute(pv_bf16,   cudaFuncAttributeMaxDynamicSharedMemorySize, 73728);
    cudaFuncSetAttribute(attn_scores_softmax, cudaFuncAttributeMaxDynamicSharedMemorySize, 147456);

    // weight splits + kerple (once per call)
    split_kernel<<<LAY*QKVN*HID/8/256, 256>>>(Wqkv_w, wqkv_hi, wqkv_lo);
    split_kernel<<<LAY*HID*HID/8/256, 256>>>(aow, wao_hi, wao_lo);
    glu_split_kernel<<<(int)((size_t)LAY*2*INTER*96/256), 256>>>(gluw, wglu_hi, wglu_lo);
    split_kernel<<<(int)((size_t)LAY*HID*INTER/8/256), 256>>>(wow, wwo_hi, wwo_lo);
    kerple_kernel<<<LAY, SS>>>(r1, r2, r3, kb);

    mask_init_kernel<<<TOK*HID2/256, 256>>>(hs, mask, h, h_hi, h_lo);

    for (int l = 0; l < LAY; l++) {
        gemm_bf16<<<dim3(QKVN/128, TOK/128), 256, 98304>>>(
            h_hi, h_lo, wqkv_hi + (size_t)l*QKVN*HID/2, wqkv_lo + (size_t)l*QKVN*HID/2,
            Wqkv_b + (size_t)l*QKVN, nullptr, mask, nullptr, qkv_hi, qkv_lo,
            TOK, QKVN, HID);

        transpose_v_kernel<<<dim3(BNH, SS/128), 256>>>(qkv_hi, qkv_lo, vt_hi, vt_lo);
        attn_scores_softmax<<<dim3(SS/64, BNH), 256, 147456>>>(
            qkv_hi, qkv_lo, mask, kb + (size_t)l*NH*SS, p_hi, p_lo);
        pv_bf16<<<dim3(BNH, SS/128), 256, 73728>>>(p_hi, p_lo, vt_hi, vt_lo, at_hi, at_lo);

        gemm_bf16<<<dim3(HID/128, TOK/128), 256, 98304>>>(
            at_hi, at_lo, wao_hi + (size_t)l*HID*HID/2, wao_lo + (size_t)l*HID*HID/2,
            aob + (size_t)l*HID, h, nullptr, y, nullptr, nullptr,
            TOK, HID, HID);
        ln_kernel<<<TOK, 384>>>(y, ln1g + (size_t)l*HID, ln1b + (size_t)l*HID, mask,
                                ao, ao_hi, ao_lo);

        gemm_glu<<<dim3(2*INTER/128, TOK/128), 256, 98304>>>(
            ao_hi, ao_lo, wglu_hi + (size_t)l*2*INTER*HID/2, wglu_lo + (size_t)l*2*INTER*HID/2,
            x_hi, x_lo, HID);

        gemm_bf16<<<dim3(HID/128, TOK/128), 256, 98304>>>(
            x_hi, x_lo, wwo_hi + (size_t)l*HID*INTER/2, wwo_lo + (size_t)l*HID*INTER/2,
            wob + (size_t)l*HID, ao, nullptr, y, nullptr, nullptr,
            TOK, HID, INTER);

        float* hout = (l == LAY-1) ? (float*)d_out : h;
        ln_kernel<<<TOK, 384>>>(y, ln2g + (size_t)l*HID, ln2b + (size_t)l*HID, mask,
                                hout, h_hi, h_lo);
    }
}